// round 15
// baseline (speedup 1.0000x reference)
#include <cuda_runtime.h>
#include <cuda_fp16.h>
#include <math.h>
#include <stdint.h>

// Problem constants
#define BB 4
#define TT 1024
#define DD 1024
#define HH 16
#define HDIM 64
#define LL 8
#define VV 50257
#define VPAD 50432              // multiple of 256
#define NT2LM ((VPAD/256)*2)    // 394 logsumexp partials per row
#define ROWS (BB*TT)            // 4096
#define SCALE_ATT 0.07216878364870322f  // 1/sqrt(192)

// ---------------------------------------------------------------------------
// Scratch (static device globals; no runtime allocation)
// ---------------------------------------------------------------------------
__device__ float g_x   [ (size_t)ROWS * DD ];
__device__ float g_nll [ ROWS ];
__device__ float2 g_part[ (size_t)ROWS * NT2LM ];
// plain fp16 activations
__device__ __half g_qkvh[ (size_t)ROWS * 3 * DD ];
__device__ __half g_h  [ (size_t)ROWS * DD ];
__device__ __half g_y  [ (size_t)ROWS * DD ];
__device__ __half g_m  [ (size_t)ROWS * 4 * DD ];
__device__ __half g_xh [ (size_t)ROWS * DD ];
// fp16 transposed weights ([N,K] row-major)
__device__ __half g_wqkvT [ (size_t)LL * 3*DD * DD ];
__device__ __half g_wprojT[ (size_t)LL * DD * DD ];
__device__ __half g_w1T   [ (size_t)LL * 4*DD * DD ];
__device__ __half g_w2T   [ (size_t)LL * DD * 4*DD ];
__device__ __half g_lmwT  [ (size_t)VPAD * DD ];

// ---------------------------------------------------------------------------
// helpers
// ---------------------------------------------------------------------------
__device__ __forceinline__ uint32_t smem_u32(const void* p) {
    uint32_t a;
    asm("{ .reg .u64 t; cvta.to.shared.u64 t, %1; cvt.u32.u64 %0, t; }"
        : "=r"(a) : "l"(p));
    return a;
}
__device__ __forceinline__ uint32_t pack2(float x, float y) {
    __half hx = __float2half_rn(x);
    __half hy = __float2half_rn(y);
    return (uint32_t)__half_as_ushort(hx) | ((uint32_t)__half_as_ushort(hy) << 16);
}

#define MMA_F32(d, a, b) \
    asm volatile("mma.sync.aligned.m16n8k16.row.col.f32.f16.f16.f32 " \
        "{%0,%1,%2,%3}, {%4,%5,%6,%7}, {%8,%9}, {%0,%1,%2,%3};" \
        : "+f"((d)[0]), "+f"((d)[1]), "+f"((d)[2]), "+f"((d)[3]) \
        : "r"((a)[0]), "r"((a)[1]), "r"((a)[2]), "r"((a)[3]), \
          "r"((b)[0]), "r"((b)[1]))

#define LDSM4(r0, r1, r2, r3, addr) \
    asm volatile("ldmatrix.sync.aligned.m8n8.x4.shared.b16 {%0,%1,%2,%3}, [%4];" \
        : "=r"(r0), "=r"(r1), "=r"(r2), "=r"(r3) : "r"(addr))

#define LDSM4T(r0, r1, r2, r3, addr) \
    asm volatile("ldmatrix.sync.aligned.m8n8.x4.trans.shared.b16 {%0,%1,%2,%3}, [%4];" \
        : "=r"(r0), "=r"(r1), "=r"(r2), "=r"(r3) : "r"(addr))

__device__ __forceinline__ void cp16(uint32_t d, const void* g) {
    asm volatile("cp.async.cg.shared.global [%0], [%1], 16;" :: "r"(d), "l"(g));
}
#define CP_COMMIT() asm volatile("cp.async.commit_group;" ::: "memory")
#define CP_WAIT0()  asm volatile("cp.async.wait_group 0;" ::: "memory")
#define CP_WAIT1()  asm volatile("cp.async.wait_group 1;" ::: "memory")

// ---------------------------------------------------------------------------
// fp16 tensor GEMM: C[M,N] = A[M,K] @ Bt[N,K]^T (+bias)(+relu/+res)
// CTA tile 128x256, K-chunk 64, 2-stage cp.async, 512 threads.
// EPI: 0=bias->f32 (+opt lse partials), 1=bias+relu->fp16,
//      2=+res->f32 (+opt fp16 dual-write), 3=bias->fp16.
// ---------------------------------------------------------------------------
#define PITCH 144
#define ATILE (128*PITCH)        // 18432
#define BTILE (256*PITCH)        // 36864
#define BUFB  (ATILE + BTILE)    // 55296
#define SMEM_DYN (2*BUFB)        // 110592

template<int EPI>
__global__ __launch_bounds__(512) void hgemm_kernel(
    int M, int N, int K,
    const __half* __restrict__ A, const __half* __restrict__ Bt,
    const float* __restrict__ bias, const float* __restrict__ res,
    float* __restrict__ C, __half* __restrict__ Ch,
    float2* __restrict__ part)
{
    extern __shared__ __align__(128) char smem[];
    const uint32_t sb = smem_u32(smem);
    const int tid  = threadIdx.x;
    const int wid  = tid >> 5;
    const int lane = tid & 31;
    const int mbase = blockIdx.x * 128;
    const int nbase = blockIdx.y * 256;
    const int warp_m = wid & 3;
    const int warp_n = wid >> 2;
    const int g = lane >> 2;
    const int q = lane & 3;

    const uint32_t aoff = (uint32_t)(warp_m*32 + (lane & 15)) * PITCH
                        + ((lane >> 4) & 1) * 16;
    const uint32_t boff = ATILE
                        + (uint32_t)(warp_n*64 + (lane & 7) + ((lane >> 4) & 1)*8) * PITCH
                        + ((lane >> 3) & 1) * 16;

    float acc[2][8][4];
    #pragma unroll
    for (int m = 0; m < 2; m++)
        #pragma unroll
        for (int n = 0; n < 8; n++)
            #pragma unroll
            for (int r = 0; r < 4; r++) acc[m][n][r] = 0.0f;

    const int nch = K >> 6;

    auto issue = [&](uint32_t dstbase, int k0) {
        #pragma unroll
        for (int i = 0; i < 2; i++) {
            int v = i*512 + tid;
            int row = v >> 3, seg = v & 7;
            cp16(dstbase + (uint32_t)row*PITCH + seg*16,
                 A + (size_t)(mbase+row)*K + k0 + seg*8);
        }
        #pragma unroll
        for (int i = 0; i < 4; i++) {
            int v = i*512 + tid;
            int row = v >> 3, seg = v & 7;
            cp16(dstbase + ATILE + (uint32_t)row*PITCH + seg*16,
                 Bt + (size_t)(nbase+row)*K + k0 + seg*8);
        }
    };

    issue(sb, 0);
    CP_COMMIT();

    for (int it = 0; it < nch; it++) {
        if (it + 1 < nch) {
            issue(sb + ((it+1) & 1) * BUFB, (it+1) << 6);
            CP_COMMIT();
            CP_WAIT1();
        } else {
            CP_WAIT0();
        }
        __syncthreads();

        const uint32_t bufu = sb + (it & 1) * BUFB;

        #pragma unroll
        for (int ks = 0; ks < 64; ks += 16) {
            uint32_t ar[2][4], bh[8][2];
            #pragma unroll
            for (int m = 0; m < 2; m++) {
                uint32_t ad = bufu + aoff + m*(16*PITCH) + ks*2;
                LDSM4(ar[m][0], ar[m][1], ar[m][2], ar[m][3], ad);
            }
            #pragma unroll
            for (int n2 = 0; n2 < 4; n2++) {
                uint32_t bd = bufu + boff + (uint32_t)n2*(16*PITCH) + ks*2;
                uint32_t r0, r1, r2, r3;
                LDSM4(r0, r1, r2, r3, bd);
                bh[n2*2][0] = r0; bh[n2*2][1] = r1;
                bh[n2*2+1][0] = r2; bh[n2*2+1][1] = r3;
            }
            #pragma unroll
            for (int m = 0; m < 2; m++)
                #pragma unroll
                for (int n = 0; n < 8; n++)
                    MMA_F32(acc[m][n], ar[m], bh[n]);
        }
        __syncthreads();
    }

    // epilogue: two 128-col halves staged through smem
    float* Cs = (float*)smem;   // [128][132]
    #pragma unroll
    for (int half = 0; half < 2; half++) {
        if ((warp_n >> 1) == half) {
            int cb = (warp_n & 1) * 64;
            #pragma unroll
            for (int m = 0; m < 2; m++) {
                int r0 = warp_m*32 + m*16 + g;
                #pragma unroll
                for (int n = 0; n < 8; n++) {
                    int col = cb + n*8 + 2*q;
                    Cs[r0*132 + col]       = acc[m][n][0];
                    Cs[r0*132 + col + 1]   = acc[m][n][1];
                    Cs[(r0+8)*132 + col]   = acc[m][n][2];
                    Cs[(r0+8)*132 + col+1] = acc[m][n][3];
                }
            }
        }
        __syncthreads();

        const int nb = nbase + half*128;
        if (EPI == 1 || EPI == 3) {
            #pragma unroll
            for (int i = 0; i < 8; i++) {
                int u = tid + i*512;
                int row = u >> 5, c4 = (u & 31) * 4;
                int col = nb + c4;
                float v0 = Cs[row*132 + c4 + 0] + bias[col];
                float v1 = Cs[row*132 + c4 + 1] + bias[col+1];
                float v2 = Cs[row*132 + c4 + 2] + bias[col+2];
                float v3 = Cs[row*132 + c4 + 3] + bias[col+3];
                if (EPI == 1) {
                    v0 = fmaxf(v0, 0.f); v1 = fmaxf(v1, 0.f);
                    v2 = fmaxf(v2, 0.f); v3 = fmaxf(v3, 0.f);
                }
                uint2 hv;
                hv.x = pack2(v0, v1);
                hv.y = pack2(v2, v3);
                *(uint2*)(Ch + (size_t)(mbase+row)*N + col) = hv;
            }
        } else if ((N & 3) == 0) {
            #pragma unroll
            for (int i = 0; i < 8; i++) {
                int u = tid + i*512;
                int row = u >> 5, c4 = (u & 31) * 4;
                int col = nb + c4;
                float v0 = Cs[row*132 + c4 + 0];
                float v1 = Cs[row*132 + c4 + 1];
                float v2 = Cs[row*132 + c4 + 2];
                float v3 = Cs[row*132 + c4 + 3];
                if (bias) { v0 += bias[col]; v1 += bias[col+1]; v2 += bias[col+2]; v3 += bias[col+3]; }
                if (EPI == 2) {
                    const float4 rv = *(const float4*)(res + (size_t)(mbase+row)*N + col);
                    v0 += rv.x; v1 += rv.y; v2 += rv.z; v3 += rv.w;
                }
                *(float4*)(C + (size_t)(mbase+row)*N + col) = make_float4(v0, v1, v2, v3);
                if (EPI == 2 && Ch != nullptr) {
                    uint2 hv;
                    hv.x = pack2(v0, v1);
                    hv.y = pack2(v2, v3);
                    *(uint2*)(Ch + (size_t)(mbase+row)*N + col) = hv;
                }
            }
        } else {
            // ragged-N path (LM head)
            #pragma unroll
            for (int i = 0; i < 8; i++) {
                int u = tid + i*512;
                int row = u >> 5, c4 = (u & 31) * 4;
                float* crow = C + (size_t)(mbase+row)*N;
                float v[4];
                #pragma unroll
                for (int j = 0; j < 4; j++) {
                    int col = nb + c4 + j;
                    if (col < N) {
                        float vv = Cs[row*132 + c4 + j];
                        if (bias) vv += bias[col];
                        crow[col] = vv;
                        v[j] = vv;
                    } else {
                        v[j] = -1e30f;
                    }
                }
                if (EPI == 0 && part != nullptr) {
                    float lm = fmaxf(fmaxf(v[0], v[1]), fmaxf(v[2], v[3]));
                    #pragma unroll
                    for (int o2 = 16; o2 > 0; o2 >>= 1)
                        lm = fmaxf(lm, __shfl_xor_sync(0xffffffffu, lm, o2));
                    float ps = 0.0f;
                    #pragma unroll
                    for (int j = 0; j < 4; j++)
                        if (nb + c4 + j < N) ps += __expf(v[j] - lm);
                    #pragma unroll
                    for (int o2 = 16; o2 > 0; o2 >>= 1)
                        ps += __shfl_xor_sync(0xffffffffu, ps, o2);
                    if (lane == 0)
                        part[(size_t)(mbase+row)*NT2LM + blockIdx.y*2 + half]
                            = make_float2(lm, ps);
                }
            }
        }
        __syncthreads();
    }
}

// ---------------------------------------------------------------------------
// Tiled transpose to fp16: in [K,N] -> out [Npad,K], zero-pad rows >= N.
// Store phase vectorized: 4 consecutive k per thread -> uint2 (4 halves).
// ---------------------------------------------------------------------------
__global__ __launch_bounds__(256) void tp_kernel(
    const float* __restrict__ in, __half* __restrict__ out,
    int K, int N, int Npad, size_t inStride, size_t outStride)
{
    __shared__ float t[32][33];
    const float* ip = in + blockIdx.z * inStride;
    __half* op = out + blockIdx.z * outStride;
    int n0 = blockIdx.x * 32, k0 = blockIdx.y * 32;
    int tx = threadIdx.x & 31, ty = threadIdx.x >> 5;
    #pragma unroll
    for (int j = ty; j < 32; j += 8) {
        int k = k0 + j, n = n0 + tx;
        t[j][tx] = (k < K && n < N) ? ip[(size_t)k * N + n] : 0.0f;
    }
    __syncthreads();
    {
        int nl = threadIdx.x >> 3;          // 0..31
        int kk = (threadIdx.x & 7) * 4;     // 0..28
        int n = n0 + nl, k = k0 + kk;       // K % 32 == 0 always
        if (n < Npad) {
            uint2 hv;
            hv.x = pack2(t[kk+0][nl], t[kk+1][nl]);
            hv.y = pack2(t[kk+2][nl], t[kk+3][nl]);
            *(uint2*)(op + (size_t)n * K + k) = hv;
        }
    }
}

// ---------------------------------------------------------------------------
// Embedding
// ---------------------------------------------------------------------------
__global__ __launch_bounds__(256) void embed_kernel(
    const int* __restrict__ idx, const float* __restrict__ tok,
    const float* __restrict__ pos, float* __restrict__ x)
{
    int row = blockIdx.x;
    int t   = row & (TT - 1);
    int id  = idx[row];
    const float4* tp = (const float4*)(tok + (size_t)id * DD);
    const float4* pp = (const float4*)(pos + (size_t)t  * DD);
    float4*       xp = (float4*)(x + (size_t)row * DD);
    int i = threadIdx.x;
    float4 a = tp[i], b = pp[i];
    a.x += b.x; a.y += b.y; a.z += b.z; a.w += b.w;
    xp[i] = a;
}

// ---------------------------------------------------------------------------
// LayerNorm -> fp16, warp-shuffle reduction (1 sync)
// ---------------------------------------------------------------------------
__global__ __launch_bounds__(256) void ln_kernel(
    const float* __restrict__ x, const float* __restrict__ g,
    const float* __restrict__ b, __half* __restrict__ oh)
{
    __shared__ float sw[8];
    __shared__ float ssw[8];
    int row = blockIdx.x;
    int tid = threadIdx.x;
    float4 v = ((const float4*)(x + (size_t)row * DD))[tid];
    float s  = v.x + v.y + v.z + v.w;
    float ss = v.x*v.x + v.y*v.y + v.z*v.z + v.w*v.w;
    #pragma unroll
    for (int o = 16; o > 0; o >>= 1) {
        s  += __shfl_xor_sync(0xffffffffu, s, o);
        ss += __shfl_xor_sync(0xffffffffu, ss, o);
    }
    if ((tid & 31) == 0) { sw[tid >> 5] = s; ssw[tid >> 5] = ss; }
    __syncthreads();
    float ts = 0.0f, tss = 0.0f;
    #pragma unroll
    for (int w = 0; w < 8; w++) { ts += sw[w]; tss += ssw[w]; }
    float mu   = ts * (1.0f / DD);
    float var  = tss * (1.0f / DD) - mu * mu;
    float rstd = rsqrtf(var + 1e-5f);
    float4 gv = ((const float4*)g)[tid];
    float4 bv = ((const float4*)b)[tid];
    float o0 = (v.x - mu) * rstd * gv.x + bv.x;
    float o1 = (v.y - mu) * rstd * gv.y + bv.y;
    float o2 = (v.z - mu) * rstd * gv.z + bv.z;
    float o3 = (v.w - mu) * rstd * gv.w + bv.w;
    uint2 hv;
    hv.x = pack2(o0, o1);
    hv.y = pack2(o2, o3);
    *(uint2*)(oh + (size_t)row * DD + tid * 4) = hv;
}

// ---------------------------------------------------------------------------
// Tensor-core flash attention, fp16 qkv input, double-buffered cp.async K/V.
// Block = 128 threads (4 warps): one (b,h), 64-query tile. Grid (B*H, T/64).
// ---------------------------------------------------------------------------
#define APITCH 144
#define ATILE2 (64*APITCH)       // 9216

__global__ __launch_bounds__(128) void attn_kernel(
    const __half* __restrict__ qkv, __half* __restrict__ yh)
{
    __shared__ __align__(16) char sm[5 * ATILE2];   // Q | K0 K1 | V0 V1
    const uint32_t sbase = smem_u32(sm);

    const int tid  = threadIdx.x;
    const int wid  = tid >> 5;
    const int lane = tid & 31;
    const int g = lane >> 2;
    const int q = lane & 3;
    const int bh = blockIdx.x;
    const int b  = bh >> 4;
    const int h  = bh & (HH - 1);
    const int qbase = blockIdx.y * 64;

    auto issue = [&](int kt) {
        const int bsel = kt & 1;
        const int kbase = kt * 64;
        #pragma unroll
        for (int i = 0; i < 4; i++) {
            int v = i*128 + tid;
            int row = v >> 3, seg = v & 7;
            const __half* src = qkv + (size_t)(b*TT + kbase + row)*(3*DD)
                              + DD + h*HDIM + seg*8;
            uint32_t doff = (uint32_t)row*APITCH + seg*16;
            cp16(sbase + (1+bsel)*ATILE2 + doff, src);        // K
            cp16(sbase + (3+bsel)*ATILE2 + doff, src + DD);   // V
        }
    };

    {
        #pragma unroll
        for (int i = 0; i < 4; i++) {
            int v = i*128 + tid;
            int row = v >> 3, seg = v & 7;
            cp16(sbase + (uint32_t)row*APITCH + seg*16,
                 qkv + (size_t)(b*TT + qbase + row)*(3*DD) + h*HDIM + seg*8);
        }
        issue(0);
        CP_COMMIT();
    }

    const int qrow0 = qbase + wid*16 + g;
    const int qrow1 = qrow0 + 8;

    uint32_t qa[4][4];
    float m0 = -1e30f, m1 = -1e30f, l0 = 0.0f, l1 = 0.0f;
    float oacc[8][4];
    #pragma unroll
    for (int n = 0; n < 8; n++)
        #pragma unroll
        for (int r = 0; r < 4; r++) oacc[n][r] = 0.0f;

    const uint32_t kfl = (uint32_t)((lane & 7) + ((lane >> 4) & 1)*8)*APITCH
                       + ((lane >> 3) & 1) * 16;
    const uint32_t vfl = (uint32_t)((lane & 7) + ((lane >> 3) & 1)*8)*APITCH
                       + ((lane >> 4) & 1) * 16;

    const int ntiles = blockIdx.y + 1;
    for (int kt = 0; kt < ntiles; kt++) {
        const int kbase = kt * 64;
        if (kt + 1 < ntiles) {
            issue(kt + 1);
            CP_COMMIT();
            CP_WAIT1();
        } else {
            CP_WAIT0();
        }
        __syncthreads();

        if (kt == 0) {
            uint32_t qaddr = sbase + (uint32_t)(wid*16 + (lane & 15))*APITCH
                           + ((lane >> 4) & 1) * 16;
            #pragma unroll
            for (int c = 0; c < 4; c++)
                LDSM4(qa[c][0], qa[c][1], qa[c][2], qa[c][3], qaddr + c*32);
        }

        const uint32_t kfr = sbase + (1 + (kt & 1))*ATILE2 + kfl;
        const uint32_t vfr = sbase + (3 + (kt & 1))*ATILE2 + vfl;

        float s[8][4];
        #pragma unroll
        for (int n = 0; n < 8; n++)
            #pragma unroll
            for (int r = 0; r < 4; r++) s[n][r] = 0.0f;
        #pragma unroll
        for (int kc = 0; kc < 4; kc++) {
            #pragma unroll
            for (int n2 = 0; n2 < 4; n2++) {
                uint32_t r0, r1, r2, r3;
                LDSM4(r0, r1, r2, r3, kfr + (uint32_t)n2*(16*APITCH) + kc*32);
                uint32_t kb0[2] = {r0, r1};
                uint32_t kb1[2] = {r2, r3};
                MMA_F32(s[n2*2],   qa[kc], kb0);
                MMA_F32(s[n2*2+1], qa[kc], kb1);
            }
        }

        #pragma unroll
        for (int n = 0; n < 8; n++) {
            int k0 = kbase + n*8 + 2*q;
            s[n][0] = (k0     <= qrow0) ? s[n][0]*SCALE_ATT : -1e30f;
            s[n][1] = (k0 + 1 <= qrow0) ? s[n][1]*SCALE_ATT : -1e30f;
            s[n][2] = (k0     <= qrow1) ? s[n][2]*SCALE_ATT : -1e30f;
            s[n][3] = (k0 + 1 <= qrow1) ? s[n][3]*SCALE_ATT : -1e30f;
        }

        float mx0 = -1e30f, mx1 = -1e30f;
        #pragma unroll
        for (int n = 0; n < 8; n++) {
            mx0 = fmaxf(mx0, fmaxf(s[n][0], s[n][1]));
            mx1 = fmaxf(mx1, fmaxf(s[n][2], s[n][3]));
        }
        mx0 = fmaxf(mx0, __shfl_xor_sync(0xffffffffu, mx0, 1));
        mx0 = fmaxf(mx0, __shfl_xor_sync(0xffffffffu, mx0, 2));
        mx1 = fmaxf(mx1, __shfl_xor_sync(0xffffffffu, mx1, 1));
        mx1 = fmaxf(mx1, __shfl_xor_sync(0xffffffffu, mx1, 2));

        float nm0 = fmaxf(m0, mx0), nm1 = fmaxf(m1, mx1);
        float cor0 = __expf(m0 - nm0), cor1 = __expf(m1 - nm1);
        m0 = nm0; m1 = nm1;
        l0 *= cor0; l1 *= cor1;
        #pragma unroll
        for (int n = 0; n < 8; n++) {
            oacc[n][0] *= cor0; oacc[n][1] *= cor0;
            oacc[n][2] *= cor1; oacc[n][3] *= cor1;
        }

        float sum0 = 0.0f, sum1 = 0.0f;
        #pragma unroll
        for (int n = 0; n < 8; n++) {
            s[n][0] = __expf(s[n][0] - nm0); sum0 += s[n][0];
            s[n][1] = __expf(s[n][1] - nm0); sum0 += s[n][1];
            s[n][2] = __expf(s[n][2] - nm1); sum1 += s[n][2];
            s[n][3] = __expf(s[n][3] - nm1); sum1 += s[n][3];
        }
        sum0 += __shfl_xor_sync(0xffffffffu, sum0, 1);
        sum0 += __shfl_xor_sync(0xffffffffu, sum0, 2);
        sum1 += __shfl_xor_sync(0xffffffffu, sum1, 1);
        sum1 += __shfl_xor_sync(0xffffffffu, sum1, 2);
        l0 += sum0; l1 += sum1;

        #pragma unroll
        for (int kc = 0; kc < 4; kc++) {
            uint32_t pa[4];
            pa[0] = pack2(s[2*kc][0],   s[2*kc][1]);
            pa[1] = pack2(s[2*kc][2],   s[2*kc][3]);
            pa[2] = pack2(s[2*kc+1][0], s[2*kc+1][1]);
            pa[3] = pack2(s[2*kc+1][2], s[2*kc+1][3]);
            #pragma unroll
            for (int n2 = 0; n2 < 4; n2++) {
                uint32_t r0, r1, r2, r3;
                LDSM4T(r0, r1, r2, r3, vfr + (uint32_t)kc*(16*APITCH) + n2*32);
                uint32_t vb0[2] = {r0, r1};
                uint32_t vb1[2] = {r2, r3};
                MMA_F32(oacc[n2*2],   pa, vb0);
                MMA_F32(oacc[n2*2+1], pa, vb1);
            }
        }
        __syncthreads();
    }

    float inv0 = 1.0f / l0, inv1 = 1.0f / l1;
    size_t base0 = (size_t)(b*TT + qrow0) * DD + h*HDIM;
    size_t base1 = base0 + (size_t)8 * DD;
    #pragma unroll
    for (int n = 0; n < 8; n++) {
        int col = n*8 + 2*q;
        *(uint32_t*)(yh + base0 + col) = pack2(oacc[n][0]*inv0, oacc[n][1]*inv0);
        *(uint32_t*)(yh + base1 + col) = pack2(oacc[n][2]*inv1, oacc[n][3]*inv1);
    }
}

// ---------------------------------------------------------------------------
// NLL from logsumexp partials + gathered target logit
// ---------------------------------------------------------------------------
__global__ __launch_bounds__(128) void nll_kernel(
    const float2* __restrict__ part, const float* __restrict__ logits,
    const int* __restrict__ tgt, float* __restrict__ nll)
{
    __shared__ float rm[128];
    __shared__ float rs[128];
    int row = blockIdx.x;
    int tid = threadIdx.x;
    const float2* pr = part + (size_t)row * NT2LM;

    float m = -1e30f, s = 0.0f;
    for (int i = tid; i < NT2LM; i += 128) {
        float2 p = pr[i];
        float M = fmaxf(m, p.x);
        s = s * __expf(m - M) + p.y * __expf(p.x - M);
        m = M;
    }
    rm[tid] = m; rs[tid] = s;
    __syncthreads();
    for (int o = 64; o > 0; o >>= 1) {
        if (tid < o) {
            float m2 = rm[tid + o], s2 = rs[tid + o];
            float M = fmaxf(rm[tid], m2);
            rs[tid] = rs[tid] * __expf(rm[tid] - M) + s2 * __expf(m2 - M);
            rm[tid] = M;
        }
        __syncthreads();
    }
    if (tid == 0) {
        float lse = rm[0] + logf(rs[0]);
        int tg = tgt[row];
        nll[row] = (tg != 0) ? (lse - logits[(size_t)row * VV + tg]) : 0.0f;
    }
}

__global__ __launch_bounds__(256) void loss_kernel(
    const float* __restrict__ nll, const int* __restrict__ tgt,
    float* __restrict__ out)
{
    __shared__ float s[256];
    __shared__ float c[256];
    int tid = threadIdx.x;
    float sv = 0.0f, cv = 0.0f;
    for (int i = tid; i < ROWS; i += 256) {
        sv += nll[i];
        cv += (tgt[i] != 0) ? 1.0f : 0.0f;
    }
    s[tid] = sv; c[tid] = cv; __syncthreads();
    for (int o = 128; o > 0; o >>= 1) {
        if (tid < o) { s[tid] += s[tid+o]; c[tid] += c[tid+o]; }
        __syncthreads();
    }
    if (tid == 0) out[0] = s[0] / fmaxf(c[0], 1.0f);
}

// ---------------------------------------------------------------------------
// Launcher
// ---------------------------------------------------------------------------
extern "C" void kernel_launch(void* const* d_in, const int* in_sizes, int n_in,
                              void* d_out, int out_size)
{
    const int*   idx   = (const int*)  d_in[0];
    const int*   tgt   = (const int*)  d_in[1];
    const float* tok   = (const float*)d_in[2];
    const float* pos   = (const float*)d_in[3];
    const float* ln1g  = (const float*)d_in[4];
    const float* ln1b  = (const float*)d_in[5];
    const float* wqkv  = (const float*)d_in[6];
    const float* bqkv  = (const float*)d_in[7];
    const float* wproj = (const float*)d_in[8];
    const float* bproj = (const float*)d_in[9];
    const float* ln2g  = (const float*)d_in[10];
    const float* ln2b  = (const float*)d_in[11];
    const float* w1    = (const float*)d_in[12];
    const float* b1    = (const float*)d_in[13];
    const float* w2    = (const float*)d_in[14];
    const float* b2    = (const float*)d_in[15];
    const float* lmw   = (const float*)d_in[16];

    float *px, *pnll;
    float2 *ppart;
    __half *pqkvh, *ph, *py, *pm, *pxh;
    __half *pwqkv, *pwproj, *pw1, *pw2, *plmw;
    cudaGetSymbolAddress((void**)&px,    g_x);
    cudaGetSymbolAddress((void**)&pnll,  g_nll);
    cudaGetSymbolAddress((void**)&ppart, g_part);
    cudaGetSymbolAddress((void**)&pqkvh, g_qkvh);
    cudaGetSymbolAddress((void**)&ph,    g_h);
    cudaGetSymbolAddress((void**)&py,    g_y);
    cudaGetSymbolAddress((void**)&pm,    g_m);
    cudaGetSymbolAddress((void**)&pxh,   g_xh);
    cudaGetSymbolAddress((void**)&pwqkv, g_wqkvT);
    cudaGetSymbolAddress((void**)&pwproj,g_wprojT);
    cudaGetSymbolAddress((void**)&pw1,   g_w1T);
    cudaGetSymbolAddress((void**)&pw2,   g_w2T);
    cudaGetSymbolAddress((void**)&plmw,  g_lmwT);

    cudaFuncSetAttribute((const void*)hgemm_kernel<0>,
                         cudaFuncAttributeMaxDynamicSharedMemorySize, SMEM_DYN);
    cudaFuncSetAttribute((const void*)hgemm_kernel<1>,
                         cudaFuncAttributeMaxDynamicSharedMemorySize, SMEM_DYN);
    cudaFuncSetAttribute((const void*)hgemm_kernel<2>,
                         cudaFuncAttributeMaxDynamicSharedMemorySize, SMEM_DYN);
    cudaFuncSetAttribute((const void*)hgemm_kernel<3>,
                         cudaFuncAttributeMaxDynamicSharedMemorySize, SMEM_DYN);

    float* out = (float*)d_out;

    // weight transposes to fp16 (graph-captured each launch)
    tp_kernel<<<dim3(3*DD/32, DD/32, LL), 256>>>(
        wqkv, pwqkv, DD, 3*DD, 3*DD, (size_t)DD*3*DD, (size_t)3*DD*DD);
    tp_kernel<<<dim3(DD/32, DD/32, LL), 256>>>(
        wproj, pwproj, DD, DD, DD, (size_t)DD*DD, (size_t)DD*DD);
    tp_kernel<<<dim3(4*DD/32, DD/32, LL), 256>>>(
        w1, pw1, DD, 4*DD, 4*DD, (size_t)DD*4*DD, (size_t)4*DD*DD);
    tp_kernel<<<dim3(DD/32, 4*DD/32, LL), 256>>>(
        w2, pw2, 4*DD, DD, DD, (size_t)4*DD*DD, (size_t)DD*4*DD);
    tp_kernel<<<dim3(VPAD/32, DD/32, 1), 256>>>(
        lmw, plmw, DD, VV, VPAD, 0, 0);

    embed_kernel<<<ROWS, 256>>>(idx, tok, pos, px);

    for (int l = 0; l < LL; l++) {
        ln_kernel<<<ROWS, 256>>>(px, ln1g + (size_t)l*DD, ln1b + (size_t)l*DD, ph);
        hgemm_kernel<3><<<dim3(ROWS/128, 3*DD/256), 512, SMEM_DYN>>>(
            ROWS, 3*DD, DD, ph, pwqkv + (size_t)l*3*DD*DD,
            bqkv + (size_t)l*3*DD, nullptr, nullptr, pqkvh, nullptr);
        attn_kernel<<<dim3(BB*HH, TT/64), 128>>>(pqkvh, py);
        hgemm_kernel<2><<<dim3(ROWS/128, DD/256), 512, SMEM_DYN>>>(
            ROWS, DD, DD, py, pwproj + (size_t)l*DD*DD,
            bproj + (size_t)l*DD, px, px, nullptr, nullptr);
        ln_kernel<<<ROWS, 256>>>(px, ln2g + (size_t)l*DD, ln2b + (size_t)l*DD, ph);
        hgemm_kernel<1><<<dim3(ROWS/128, 4*DD/256), 512, SMEM_DYN>>>(
            ROWS, 4*DD, DD, ph, pw1 + (size_t)l*4*DD*DD,
            b1 + (size_t)l*4*DD, nullptr, nullptr, pm, nullptr);
        // last layer: dual-write fp16 residual for LM head (replaces tohalf)
        hgemm_kernel<2><<<dim3(ROWS/128, DD/256), 512, SMEM_DYN>>>(
            ROWS, DD, 4*DD, pm, pw2 + (size_t)l*DD*4*DD,
            b2 + (size_t)l*DD, px, px,
            (l == LL-1) ? pxh : nullptr, nullptr);
    }

    // logits = x @ lm_w (+ fused logsumexp partials)
    hgemm_kernel<0><<<dim3(ROWS/128, VPAD/256), 512, SMEM_DYN>>>(
        ROWS, VV, DD, pxh, plmw, nullptr, nullptr, out, nullptr, ppart);

    // loss from partials
    nll_kernel<<<ROWS, 128>>>(ppart, out, tgt, pnll);
    size_t nlog = (size_t)ROWS * VV;
    if ((size_t)out_size > nlog) {
        loss_kernel<<<1, 256>>>(pnll, tgt, out + nlog);
    }
}

// round 16
// speedup vs baseline: 1.0066x; 1.0066x over previous
#include <cuda_runtime.h>
#include <cuda_fp16.h>
#include <math.h>
#include <stdint.h>

// Problem constants
#define BB 4
#define TT 1024
#define DD 1024
#define HH 16
#define HDIM 64
#define LL 8
#define VV 50257
#define VPAD 50432              // multiple of 256
#define NT2LM ((VPAD/256)*2)    // 394 logsumexp partials per row
#define ROWS (BB*TT)            // 4096
#define SCALE_ATT 0.07216878364870322f  // 1/sqrt(192)

// ---------------------------------------------------------------------------
// Scratch (static device globals; no runtime allocation)
// ---------------------------------------------------------------------------
__device__ float g_x   [ (size_t)ROWS * DD ];
__device__ float g_nll [ ROWS ];
__device__ float2 g_part[ (size_t)ROWS * NT2LM ];
// plain fp16 activations
__device__ __half g_qkvh[ (size_t)ROWS * 3 * DD ];
__device__ __half g_h  [ (size_t)ROWS * DD ];
__device__ __half g_y  [ (size_t)ROWS * DD ];
__device__ __half g_m  [ (size_t)ROWS * 4 * DD ];
__device__ __half g_xh [ (size_t)ROWS * DD ];
// fp16 transposed weights ([N,K] row-major)
__device__ __half g_wqkvT [ (size_t)LL * 3*DD * DD ];
__device__ __half g_wprojT[ (size_t)LL * DD * DD ];
__device__ __half g_w1T   [ (size_t)LL * 4*DD * DD ];
__device__ __half g_w2T   [ (size_t)LL * DD * 4*DD ];
__device__ __half g_lmwT  [ (size_t)VPAD * DD ];

// ---------------------------------------------------------------------------
// helpers
// ---------------------------------------------------------------------------
__device__ __forceinline__ uint32_t smem_u32(const void* p) {
    uint32_t a;
    asm("{ .reg .u64 t; cvta.to.shared.u64 t, %1; cvt.u32.u64 %0, t; }"
        : "=r"(a) : "l"(p));
    return a;
}
__device__ __forceinline__ uint32_t pack2(float x, float y) {
    __half hx = __float2half_rn(x);
    __half hy = __float2half_rn(y);
    return (uint32_t)__half_as_ushort(hx) | ((uint32_t)__half_as_ushort(hy) << 16);
}

#define MMA_F32(d, a, b) \
    asm volatile("mma.sync.aligned.m16n8k16.row.col.f32.f16.f16.f32 " \
        "{%0,%1,%2,%3}, {%4,%5,%6,%7}, {%8,%9}, {%0,%1,%2,%3};" \
        : "+f"((d)[0]), "+f"((d)[1]), "+f"((d)[2]), "+f"((d)[3]) \
        : "r"((a)[0]), "r"((a)[1]), "r"((a)[2]), "r"((a)[3]), \
          "r"((b)[0]), "r"((b)[1]))

#define LDSM4(r0, r1, r2, r3, addr) \
    asm volatile("ldmatrix.sync.aligned.m8n8.x4.shared.b16 {%0,%1,%2,%3}, [%4];" \
        : "=r"(r0), "=r"(r1), "=r"(r2), "=r"(r3) : "r"(addr))

#define LDSM4T(r0, r1, r2, r3, addr) \
    asm volatile("ldmatrix.sync.aligned.m8n8.x4.trans.shared.b16 {%0,%1,%2,%3}, [%4];" \
        : "=r"(r0), "=r"(r1), "=r"(r2), "=r"(r3) : "r"(addr))

__device__ __forceinline__ void cp16(uint32_t d, const void* g) {
    asm volatile("cp.async.cg.shared.global [%0], [%1], 16;" :: "r"(d), "l"(g));
}
#define CP_COMMIT() asm volatile("cp.async.commit_group;" ::: "memory")
#define CP_WAIT0()  asm volatile("cp.async.wait_group 0;" ::: "memory")
#define CP_WAIT1()  asm volatile("cp.async.wait_group 1;" ::: "memory")

// ---------------------------------------------------------------------------
// fp16 tensor GEMM: C[M,N] = A[M,K] @ Bt[N,K]^T (+bias)(+relu/+res)
// CTA tile 128x256, K-chunk 64, 3-stage cp.async (1 sync/chunk), 512 threads.
// EPI: 0=bias->f32 (+opt lse partials), 1=bias+relu->fp16,
//      2=+res->f32 (+opt fp16 dual-write), 3=bias->fp16.
// ---------------------------------------------------------------------------
#define PITCH 144
#define ATILE (128*PITCH)        // 18432
#define BTILE (256*PITCH)        // 36864
#define BUFB  (ATILE + BTILE)    // 55296
#define SMEM_DYN (3*BUFB)        // 165888; epilogue Cs (128*132*4=67584) fits

template<int EPI>
__global__ __launch_bounds__(512) void hgemm_kernel(
    int M, int N, int K,
    const __half* __restrict__ A, const __half* __restrict__ Bt,
    const float* __restrict__ bias, const float* __restrict__ res,
    float* __restrict__ C, __half* __restrict__ Ch,
    float2* __restrict__ part)
{
    extern __shared__ __align__(128) char smem[];
    const uint32_t sb = smem_u32(smem);
    const int tid  = threadIdx.x;
    const int wid  = tid >> 5;
    const int lane = tid & 31;
    const int mbase = blockIdx.x * 128;
    const int nbase = blockIdx.y * 256;
    const int warp_m = wid & 3;
    const int warp_n = wid >> 2;
    const int g = lane >> 2;
    const int q = lane & 3;

    const uint32_t aoff = (uint32_t)(warp_m*32 + (lane & 15)) * PITCH
                        + ((lane >> 4) & 1) * 16;
    const uint32_t boff = ATILE
                        + (uint32_t)(warp_n*64 + (lane & 7) + ((lane >> 4) & 1)*8) * PITCH
                        + ((lane >> 3) & 1) * 16;

    float acc[2][8][4];
    #pragma unroll
    for (int m = 0; m < 2; m++)
        #pragma unroll
        for (int n = 0; n < 8; n++)
            #pragma unroll
            for (int r = 0; r < 4; r++) acc[m][n][r] = 0.0f;

    const int nch = K >> 6;

    auto issue = [&](uint32_t dstbase, int k0) {
        #pragma unroll
        for (int i = 0; i < 2; i++) {
            int v = i*512 + tid;
            int row = v >> 3, seg = v & 7;
            cp16(dstbase + (uint32_t)row*PITCH + seg*16,
                 A + (size_t)(mbase+row)*K + k0 + seg*8);
        }
        #pragma unroll
        for (int i = 0; i < 4; i++) {
            int v = i*512 + tid;
            int row = v >> 3, seg = v & 7;
            cp16(dstbase + ATILE + (uint32_t)row*PITCH + seg*16,
                 Bt + (size_t)(nbase+row)*K + k0 + seg*8);
        }
    };

    // prologue: 2 chunks in flight
    issue(sb, 0);
    CP_COMMIT();
    issue(sb + BUFB, 64);
    CP_COMMIT();

    for (int it = 0; it < nch; it++) {
        if (it == nch - 1) { CP_WAIT0(); } else { CP_WAIT1(); }
        __syncthreads();     // releases buf (it-1)%3 AND publishes buf it%3
        if (it + 2 < nch) {
            issue(sb + (uint32_t)((it+2) % 3) * BUFB, (it+2) << 6);
            CP_COMMIT();
        }

        const uint32_t bufu = sb + (uint32_t)(it % 3) * BUFB;

        #pragma unroll
        for (int ks = 0; ks < 64; ks += 16) {
            uint32_t ar[2][4], bh[8][2];
            #pragma unroll
            for (int m = 0; m < 2; m++) {
                uint32_t ad = bufu + aoff + m*(16*PITCH) + ks*2;
                LDSM4(ar[m][0], ar[m][1], ar[m][2], ar[m][3], ad);
            }
            #pragma unroll
            for (int n2 = 0; n2 < 4; n2++) {
                uint32_t bd = bufu + boff + (uint32_t)n2*(16*PITCH) + ks*2;
                uint32_t r0, r1, r2, r3;
                LDSM4(r0, r1, r2, r3, bd);
                bh[n2*2][0] = r0; bh[n2*2][1] = r1;
                bh[n2*2+1][0] = r2; bh[n2*2+1][1] = r3;
            }
            #pragma unroll
            for (int m = 0; m < 2; m++)
                #pragma unroll
                for (int n = 0; n < 8; n++)
                    MMA_F32(acc[m][n], ar[m], bh[n]);
        }
        // no trailing sync: next iteration's top sync protects buffer reuse
    }
    __syncthreads();

    // epilogue: two 128-col halves staged through smem
    float* Cs = (float*)smem;   // [128][132]
    #pragma unroll
    for (int half = 0; half < 2; half++) {
        if ((warp_n >> 1) == half) {
            int cb = (warp_n & 1) * 64;
            #pragma unroll
            for (int m = 0; m < 2; m++) {
                int r0 = warp_m*32 + m*16 + g;
                #pragma unroll
                for (int n = 0; n < 8; n++) {
                    int col = cb + n*8 + 2*q;
                    Cs[r0*132 + col]       = acc[m][n][0];
                    Cs[r0*132 + col + 1]   = acc[m][n][1];
                    Cs[(r0+8)*132 + col]   = acc[m][n][2];
                    Cs[(r0+8)*132 + col+1] = acc[m][n][3];
                }
            }
        }
        __syncthreads();

        const int nb = nbase + half*128;
        if (EPI == 1 || EPI == 3) {
            #pragma unroll
            for (int i = 0; i < 8; i++) {
                int u = tid + i*512;
                int row = u >> 5, c4 = (u & 31) * 4;
                int col = nb + c4;
                float v0 = Cs[row*132 + c4 + 0] + bias[col];
                float v1 = Cs[row*132 + c4 + 1] + bias[col+1];
                float v2 = Cs[row*132 + c4 + 2] + bias[col+2];
                float v3 = Cs[row*132 + c4 + 3] + bias[col+3];
                if (EPI == 1) {
                    v0 = fmaxf(v0, 0.f); v1 = fmaxf(v1, 0.f);
                    v2 = fmaxf(v2, 0.f); v3 = fmaxf(v3, 0.f);
                }
                uint2 hv;
                hv.x = pack2(v0, v1);
                hv.y = pack2(v2, v3);
                *(uint2*)(Ch + (size_t)(mbase+row)*N + col) = hv;
            }
        } else if ((N & 3) == 0) {
            #pragma unroll
            for (int i = 0; i < 8; i++) {
                int u = tid + i*512;
                int row = u >> 5, c4 = (u & 31) * 4;
                int col = nb + c4;
                float v0 = Cs[row*132 + c4 + 0];
                float v1 = Cs[row*132 + c4 + 1];
                float v2 = Cs[row*132 + c4 + 2];
                float v3 = Cs[row*132 + c4 + 3];
                if (bias) { v0 += bias[col]; v1 += bias[col+1]; v2 += bias[col+2]; v3 += bias[col+3]; }
                if (EPI == 2) {
                    const float4 rv = *(const float4*)(res + (size_t)(mbase+row)*N + col);
                    v0 += rv.x; v1 += rv.y; v2 += rv.z; v3 += rv.w;
                }
                *(float4*)(C + (size_t)(mbase+row)*N + col) = make_float4(v0, v1, v2, v3);
                if (EPI == 2 && Ch != nullptr) {
                    uint2 hv;
                    hv.x = pack2(v0, v1);
                    hv.y = pack2(v2, v3);
                    *(uint2*)(Ch + (size_t)(mbase+row)*N + col) = hv;
                }
            }
        } else {
            // ragged-N path (LM head)
            #pragma unroll
            for (int i = 0; i < 8; i++) {
                int u = tid + i*512;
                int row = u >> 5, c4 = (u & 31) * 4;
                float* crow = C + (size_t)(mbase+row)*N;
                float v[4];
                #pragma unroll
                for (int j = 0; j < 4; j++) {
                    int col = nb + c4 + j;
                    if (col < N) {
                        float vv = Cs[row*132 + c4 + j];
                        if (bias) vv += bias[col];
                        crow[col] = vv;
                        v[j] = vv;
                    } else {
                        v[j] = -1e30f;
                    }
                }
                if (EPI == 0 && part != nullptr) {
                    float lm = fmaxf(fmaxf(v[0], v[1]), fmaxf(v[2], v[3]));
                    #pragma unroll
                    for (int o2 = 16; o2 > 0; o2 >>= 1)
                        lm = fmaxf(lm, __shfl_xor_sync(0xffffffffu, lm, o2));
                    float ps = 0.0f;
                    #pragma unroll
                    for (int j = 0; j < 4; j++)
                        if (nb + c4 + j < N) ps += __expf(v[j] - lm);
                    #pragma unroll
                    for (int o2 = 16; o2 > 0; o2 >>= 1)
                        ps += __shfl_xor_sync(0xffffffffu, ps, o2);
                    if (lane == 0)
                        part[(size_t)(mbase+row)*NT2LM + blockIdx.y*2 + half]
                            = make_float2(lm, ps);
                }
            }
        }
        __syncthreads();
    }
}

// ---------------------------------------------------------------------------
// Tiled transpose to fp16: in [K,N] -> out [Npad,K], zero-pad rows >= N.
// ---------------------------------------------------------------------------
__global__ __launch_bounds__(256) void tp_kernel(
    const float* __restrict__ in, __half* __restrict__ out,
    int K, int N, int Npad, size_t inStride, size_t outStride)
{
    __shared__ float t[32][33];
    const float* ip = in + blockIdx.z * inStride;
    __half* op = out + blockIdx.z * outStride;
    int n0 = blockIdx.x * 32, k0 = blockIdx.y * 32;
    int tx = threadIdx.x & 31, ty = threadIdx.x >> 5;
    #pragma unroll
    for (int j = ty; j < 32; j += 8) {
        int k = k0 + j, n = n0 + tx;
        t[j][tx] = (k < K && n < N) ? ip[(size_t)k * N + n] : 0.0f;
    }
    __syncthreads();
    {
        int nl = threadIdx.x >> 3;
        int kk = (threadIdx.x & 7) * 4;
        int n = n0 + nl, k = k0 + kk;
        if (n < Npad) {
            uint2 hv;
            hv.x = pack2(t[kk+0][nl], t[kk+1][nl]);
            hv.y = pack2(t[kk+2][nl], t[kk+3][nl]);
            *(uint2*)(op + (size_t)n * K + k) = hv;
        }
    }
}

// ---------------------------------------------------------------------------
// Embedding
// ---------------------------------------------------------------------------
__global__ __launch_bounds__(256) void embed_kernel(
    const int* __restrict__ idx, const float* __restrict__ tok,
    const float* __restrict__ pos, float* __restrict__ x)
{
    int row = blockIdx.x;
    int t   = row & (TT - 1);
    int id  = idx[row];
    const float4* tp = (const float4*)(tok + (size_t)id * DD);
    const float4* pp = (const float4*)(pos + (size_t)t  * DD);
    float4*       xp = (float4*)(x + (size_t)row * DD);
    int i = threadIdx.x;
    float4 a = tp[i], b = pp[i];
    a.x += b.x; a.y += b.y; a.z += b.z; a.w += b.w;
    xp[i] = a;
}

// ---------------------------------------------------------------------------
// LayerNorm -> fp16, warp-shuffle reduction
// ---------------------------------------------------------------------------
__global__ __launch_bounds__(256) void ln_kernel(
    const float* __restrict__ x, const float* __restrict__ g,
    const float* __restrict__ b, __half* __restrict__ oh)
{
    __shared__ float sw[8];
    __shared__ float ssw[8];
    int row = blockIdx.x;
    int tid = threadIdx.x;
    float4 v = ((const float4*)(x + (size_t)row * DD))[tid];
    float s  = v.x + v.y + v.z + v.w;
    float ss = v.x*v.x + v.y*v.y + v.z*v.z + v.w*v.w;
    #pragma unroll
    for (int o = 16; o > 0; o >>= 1) {
        s  += __shfl_xor_sync(0xffffffffu, s, o);
        ss += __shfl_xor_sync(0xffffffffu, ss, o);
    }
    if ((tid & 31) == 0) { sw[tid >> 5] = s; ssw[tid >> 5] = ss; }
    __syncthreads();
    float ts = 0.0f, tss = 0.0f;
    #pragma unroll
    for (int w = 0; w < 8; w++) { ts += sw[w]; tss += ssw[w]; }
    float mu   = ts * (1.0f / DD);
    float var  = tss * (1.0f / DD) - mu * mu;
    float rstd = rsqrtf(var + 1e-5f);
    float4 gv = ((const float4*)g)[tid];
    float4 bv = ((const float4*)b)[tid];
    float o0 = (v.x - mu) * rstd * gv.x + bv.x;
    float o1 = (v.y - mu) * rstd * gv.y + bv.y;
    float o2 = (v.z - mu) * rstd * gv.z + bv.z;
    float o3 = (v.w - mu) * rstd * gv.w + bv.w;
    uint2 hv;
    hv.x = pack2(o0, o1);
    hv.y = pack2(o2, o3);
    *(uint2*)(oh + (size_t)row * DD + tid * 4) = hv;
}

// ---------------------------------------------------------------------------
// Tensor-core flash attention, fp16 qkv input, double-buffered cp.async K/V.
// Block = 128 threads (4 warps): one (b,h), 64-query tile. Grid (B*H, T/64).
// ---------------------------------------------------------------------------
#define APITCH 144
#define ATILE2 (64*APITCH)       // 9216

__global__ __launch_bounds__(128) void attn_kernel(
    const __half* __restrict__ qkv, __half* __restrict__ yh)
{
    __shared__ __align__(16) char sm[5 * ATILE2];   // Q | K0 K1 | V0 V1
    const uint32_t sbase = smem_u32(sm);

    const int tid  = threadIdx.x;
    const int wid  = tid >> 5;
    const int lane = tid & 31;
    const int g = lane >> 2;
    const int q = lane & 3;
    const int bh = blockIdx.x;
    const int b  = bh >> 4;
    const int h  = bh & (HH - 1);
    const int qbase = blockIdx.y * 64;

    auto issue = [&](int kt) {
        const int bsel = kt & 1;
        const int kbase = kt * 64;
        #pragma unroll
        for (int i = 0; i < 4; i++) {
            int v = i*128 + tid;
            int row = v >> 3, seg = v & 7;
            const __half* src = qkv + (size_t)(b*TT + kbase + row)*(3*DD)
                              + DD + h*HDIM + seg*8;
            uint32_t doff = (uint32_t)row*APITCH + seg*16;
            cp16(sbase + (1+bsel)*ATILE2 + doff, src);        // K
            cp16(sbase + (3+bsel)*ATILE2 + doff, src + DD);   // V
        }
    };

    {
        #pragma unroll
        for (int i = 0; i < 4; i++) {
            int v = i*128 + tid;
            int row = v >> 3, seg = v & 7;
            cp16(sbase + (uint32_t)row*APITCH + seg*16,
                 qkv + (size_t)(b*TT + qbase + row)*(3*DD) + h*HDIM + seg*8);
        }
        issue(0);
        CP_COMMIT();
    }

    const int qrow0 = qbase + wid*16 + g;
    const int qrow1 = qrow0 + 8;

    uint32_t qa[4][4];
    float m0 = -1e30f, m1 = -1e30f, l0 = 0.0f, l1 = 0.0f;
    float oacc[8][4];
    #pragma unroll
    for (int n = 0; n < 8; n++)
        #pragma unroll
        for (int r = 0; r < 4; r++) oacc[n][r] = 0.0f;

    const uint32_t kfl = (uint32_t)((lane & 7) + ((lane >> 4) & 1)*8)*APITCH
                       + ((lane >> 3) & 1) * 16;
    const uint32_t vfl = (uint32_t)((lane & 7) + ((lane >> 3) & 1)*8)*APITCH
                       + ((lane >> 4) & 1) * 16;

    const int ntiles = blockIdx.y + 1;
    for (int kt = 0; kt < ntiles; kt++) {
        const int kbase = kt * 64;
        if (kt + 1 < ntiles) {
            issue(kt + 1);
            CP_COMMIT();
            CP_WAIT1();
        } else {
            CP_WAIT0();
        }
        __syncthreads();

        if (kt == 0) {
            uint32_t qaddr = sbase + (uint32_t)(wid*16 + (lane & 15))*APITCH
                           + ((lane >> 4) & 1) * 16;
            #pragma unroll
            for (int c = 0; c < 4; c++)
                LDSM4(qa[c][0], qa[c][1], qa[c][2], qa[c][3], qaddr + c*32);
        }

        const uint32_t kfr = sbase + (1 + (kt & 1))*ATILE2 + kfl;
        const uint32_t vfr = sbase + (3 + (kt & 1))*ATILE2 + vfl;

        float s[8][4];
        #pragma unroll
        for (int n = 0; n < 8; n++)
            #pragma unroll
            for (int r = 0; r < 4; r++) s[n][r] = 0.0f;
        #pragma unroll
        for (int kc = 0; kc < 4; kc++) {
            #pragma unroll
            for (int n2 = 0; n2 < 4; n2++) {
                uint32_t r0, r1, r2, r3;
                LDSM4(r0, r1, r2, r3, kfr + (uint32_t)n2*(16*APITCH) + kc*32);
                uint32_t kb0[2] = {r0, r1};
                uint32_t kb1[2] = {r2, r3};
                MMA_F32(s[n2*2],   qa[kc], kb0);
                MMA_F32(s[n2*2+1], qa[kc], kb1);
            }
        }

        #pragma unroll
        for (int n = 0; n < 8; n++) {
            int k0 = kbase + n*8 + 2*q;
            s[n][0] = (k0     <= qrow0) ? s[n][0]*SCALE_ATT : -1e30f;
            s[n][1] = (k0 + 1 <= qrow0) ? s[n][1]*SCALE_ATT : -1e30f;
            s[n][2] = (k0     <= qrow1) ? s[n][2]*SCALE_ATT : -1e30f;
            s[n][3] = (k0 + 1 <= qrow1) ? s[n][3]*SCALE_ATT : -1e30f;
        }

        float mx0 = -1e30f, mx1 = -1e30f;
        #pragma unroll
        for (int n = 0; n < 8; n++) {
            mx0 = fmaxf(mx0, fmaxf(s[n][0], s[n][1]));
            mx1 = fmaxf(mx1, fmaxf(s[n][2], s[n][3]));
        }
        mx0 = fmaxf(mx0, __shfl_xor_sync(0xffffffffu, mx0, 1));
        mx0 = fmaxf(mx0, __shfl_xor_sync(0xffffffffu, mx0, 2));
        mx1 = fmaxf(mx1, __shfl_xor_sync(0xffffffffu, mx1, 1));
        mx1 = fmaxf(mx1, __shfl_xor_sync(0xffffffffu, mx1, 2));

        float nm0 = fmaxf(m0, mx0), nm1 = fmaxf(m1, mx1);
        float cor0 = __expf(m0 - nm0), cor1 = __expf(m1 - nm1);
        m0 = nm0; m1 = nm1;
        l0 *= cor0; l1 *= cor1;
        #pragma unroll
        for (int n = 0; n < 8; n++) {
            oacc[n][0] *= cor0; oacc[n][1] *= cor0;
            oacc[n][2] *= cor1; oacc[n][3] *= cor1;
        }

        float sum0 = 0.0f, sum1 = 0.0f;
        #pragma unroll
        for (int n = 0; n < 8; n++) {
            s[n][0] = __expf(s[n][0] - nm0); sum0 += s[n][0];
            s[n][1] = __expf(s[n][1] - nm0); sum0 += s[n][1];
            s[n][2] = __expf(s[n][2] - nm1); sum1 += s[n][2];
            s[n][3] = __expf(s[n][3] - nm1); sum1 += s[n][3];
        }
        sum0 += __shfl_xor_sync(0xffffffffu, sum0, 1);
        sum0 += __shfl_xor_sync(0xffffffffu, sum0, 2);
        sum1 += __shfl_xor_sync(0xffffffffu, sum1, 1);
        sum1 += __shfl_xor_sync(0xffffffffu, sum1, 2);
        l0 += sum0; l1 += sum1;

        #pragma unroll
        for (int kc = 0; kc < 4; kc++) {
            uint32_t pa[4];
            pa[0] = pack2(s[2*kc][0],   s[2*kc][1]);
            pa[1] = pack2(s[2*kc][2],   s[2*kc][3]);
            pa[2] = pack2(s[2*kc+1][0], s[2*kc+1][1]);
            pa[3] = pack2(s[2*kc+1][2], s[2*kc+1][3]);
            #pragma unroll
            for (int n2 = 0; n2 < 4; n2++) {
                uint32_t r0, r1, r2, r3;
                LDSM4T(r0, r1, r2, r3, vfr + (uint32_t)kc*(16*APITCH) + n2*32);
                uint32_t vb0[2] = {r0, r1};
                uint32_t vb1[2] = {r2, r3};
                MMA_F32(oacc[n2*2],   pa, vb0);
                MMA_F32(oacc[n2*2+1], pa, vb1);
            }
        }
        __syncthreads();
    }

    float inv0 = 1.0f / l0, inv1 = 1.0f / l1;
    size_t base0 = (size_t)(b*TT + qrow0) * DD + h*HDIM;
    size_t base1 = base0 + (size_t)8 * DD;
    #pragma unroll
    for (int n = 0; n < 8; n++) {
        int col = n*8 + 2*q;
        *(uint32_t*)(yh + base0 + col) = pack2(oacc[n][0]*inv0, oacc[n][1]*inv0);
        *(uint32_t*)(yh + base1 + col) = pack2(oacc[n][2]*inv1, oacc[n][3]*inv1);
    }
}

// ---------------------------------------------------------------------------
// NLL from logsumexp partials + gathered target logit
// ---------------------------------------------------------------------------
__global__ __launch_bounds__(128) void nll_kernel(
    const float2* __restrict__ part, const float* __restrict__ logits,
    const int* __restrict__ tgt, float* __restrict__ nll)
{
    __shared__ float rm[128];
    __shared__ float rs[128];
    int row = blockIdx.x;
    int tid = threadIdx.x;
    const float2* pr = part + (size_t)row * NT2LM;

    float m = -1e30f, s = 0.0f;
    for (int i = tid; i < NT2LM; i += 128) {
        float2 p = pr[i];
        float M = fmaxf(m, p.x);
        s = s * __expf(m - M) + p.y * __expf(p.x - M);
        m = M;
    }
    rm[tid] = m; rs[tid] = s;
    __syncthreads();
    for (int o = 64; o > 0; o >>= 1) {
        if (tid < o) {
            float m2 = rm[tid + o], s2 = rs[tid + o];
            float M = fmaxf(rm[tid], m2);
            rs[tid] = rs[tid] * __expf(rm[tid] - M) + s2 * __expf(m2 - M);
            rm[tid] = M;
        }
        __syncthreads();
    }
    if (tid == 0) {
        float lse = rm[0] + logf(rs[0]);
        int tg = tgt[row];
        nll[row] = (tg != 0) ? (lse - logits[(size_t)row * VV + tg]) : 0.0f;
    }
}

__global__ __launch_bounds__(256) void loss_kernel(
    const float* __restrict__ nll, const int* __restrict__ tgt,
    float* __restrict__ out)
{
    __shared__ float s[256];
    __shared__ float c[256];
    int tid = threadIdx.x;
    float sv = 0.0f, cv = 0.0f;
    for (int i = tid; i < ROWS; i += 256) {
        sv += nll[i];
        cv += (tgt[i] != 0) ? 1.0f : 0.0f;
    }
    s[tid] = sv; c[tid] = cv; __syncthreads();
    for (int o = 128; o > 0; o >>= 1) {
        if (tid < o) { s[tid] += s[tid+o]; c[tid] += c[tid+o]; }
        __syncthreads();
    }
    if (tid == 0) out[0] = s[0] / fmaxf(c[0], 1.0f);
}

// ---------------------------------------------------------------------------
// Launcher
// ---------------------------------------------------------------------------
extern "C" void kernel_launch(void* const* d_in, const int* in_sizes, int n_in,
                              void* d_out, int out_size)
{
    const int*   idx   = (const int*)  d_in[0];
    const int*   tgt   = (const int*)  d_in[1];
    const float* tok   = (const float*)d_in[2];
    const float* pos   = (const float*)d_in[3];
    const float* ln1g  = (const float*)d_in[4];
    const float* ln1b  = (const float*)d_in[5];
    const float* wqkv  = (const float*)d_in[6];
    const float* bqkv  = (const float*)d_in[7];
    const float* wproj = (const float*)d_in[8];
    const float* bproj = (const float*)d_in[9];
    const float* ln2g  = (const float*)d_in[10];
    const float* ln2b  = (const float*)d_in[11];
    const float* w1    = (const float*)d_in[12];
    const float* b1    = (const float*)d_in[13];
    const float* w2    = (const float*)d_in[14];
    const float* b2    = (const float*)d_in[15];
    const float* lmw   = (const float*)d_in[16];

    float *px, *pnll;
    float2 *ppart;
    __half *pqkvh, *ph, *py, *pm, *pxh;
    __half *pwqkv, *pwproj, *pw1, *pw2, *plmw;
    cudaGetSymbolAddress((void**)&px,    g_x);
    cudaGetSymbolAddress((void**)&pnll,  g_nll);
    cudaGetSymbolAddress((void**)&ppart, g_part);
    cudaGetSymbolAddress((void**)&pqkvh, g_qkvh);
    cudaGetSymbolAddress((void**)&ph,    g_h);
    cudaGetSymbolAddress((void**)&py,    g_y);
    cudaGetSymbolAddress((void**)&pm,    g_m);
    cudaGetSymbolAddress((void**)&pxh,   g_xh);
    cudaGetSymbolAddress((void**)&pwqkv, g_wqkvT);
    cudaGetSymbolAddress((void**)&pwproj,g_wprojT);
    cudaGetSymbolAddress((void**)&pw1,   g_w1T);
    cudaGetSymbolAddress((void**)&pw2,   g_w2T);
    cudaGetSymbolAddress((void**)&plmw,  g_lmwT);

    cudaFuncSetAttribute((const void*)hgemm_kernel<0>,
                         cudaFuncAttributeMaxDynamicSharedMemorySize, SMEM_DYN);
    cudaFuncSetAttribute((const void*)hgemm_kernel<1>,
                         cudaFuncAttributeMaxDynamicSharedMemorySize, SMEM_DYN);
    cudaFuncSetAttribute((const void*)hgemm_kernel<2>,
                         cudaFuncAttributeMaxDynamicSharedMemorySize, SMEM_DYN);
    cudaFuncSetAttribute((const void*)hgemm_kernel<3>,
                         cudaFuncAttributeMaxDynamicSharedMemorySize, SMEM_DYN);

    float* out = (float*)d_out;

    // weight transposes to fp16 (graph-captured each launch)
    tp_kernel<<<dim3(3*DD/32, DD/32, LL), 256>>>(
        wqkv, pwqkv, DD, 3*DD, 3*DD, (size_t)DD*3*DD, (size_t)3*DD*DD);
    tp_kernel<<<dim3(DD/32, DD/32, LL), 256>>>(
        wproj, pwproj, DD, DD, DD, (size_t)DD*DD, (size_t)DD*DD);
    tp_kernel<<<dim3(4*DD/32, DD/32, LL), 256>>>(
        w1, pw1, DD, 4*DD, 4*DD, (size_t)DD*4*DD, (size_t)4*DD*DD);
    tp_kernel<<<dim3(DD/32, 4*DD/32, LL), 256>>>(
        w2, pw2, 4*DD, DD, DD, (size_t)4*DD*DD, (size_t)DD*4*DD);
    tp_kernel<<<dim3(VPAD/32, DD/32, 1), 256>>>(
        lmw, plmw, DD, VV, VPAD, 0, 0);

    embed_kernel<<<ROWS, 256>>>(idx, tok, pos, px);

    for (int l = 0; l < LL; l++) {
        ln_kernel<<<ROWS, 256>>>(px, ln1g + (size_t)l*DD, ln1b + (size_t)l*DD, ph);
        hgemm_kernel<3><<<dim3(ROWS/128, 3*DD/256), 512, SMEM_DYN>>>(
            ROWS, 3*DD, DD, ph, pwqkv + (size_t)l*3*DD*DD,
            bqkv + (size_t)l*3*DD, nullptr, nullptr, pqkvh, nullptr);
        attn_kernel<<<dim3(BB*HH, TT/64), 128>>>(pqkvh, py);
        hgemm_kernel<2><<<dim3(ROWS/128, DD/256), 512, SMEM_DYN>>>(
            ROWS, DD, DD, py, pwproj + (size_t)l*DD*DD,
            bproj + (size_t)l*DD, px, px, nullptr, nullptr);
        ln_kernel<<<ROWS, 256>>>(px, ln2g + (size_t)l*DD, ln2b + (size_t)l*DD, ph);
        hgemm_kernel<1><<<dim3(ROWS/128, 4*DD/256), 512, SMEM_DYN>>>(
            ROWS, 4*DD, DD, ph, pw1 + (size_t)l*4*DD*DD,
            b1 + (size_t)l*4*DD, nullptr, nullptr, pm, nullptr);
        // last layer: dual-write fp16 residual for LM head
        hgemm_kernel<2><<<dim3(ROWS/128, DD/256), 512, SMEM_DYN>>>(
            ROWS, DD, 4*DD, pm, pw2 + (size_t)l*DD*4*DD,
            b2 + (size_t)l*DD, px, px,
            (l == LL-1) ? pxh : nullptr, nullptr);
    }

    // logits = x @ lm_w (+ fused logsumexp partials)
    hgemm_kernel<0><<<dim3(ROWS/128, VPAD/256), 512, SMEM_DYN>>>(
        ROWS, VV, DD, pxh, plmw, nullptr, nullptr, out, nullptr, ppart);

    // loss from partials
    nll_kernel<<<ROWS, 128>>>(ppart, out, tgt, pnll);
    size_t nlog = (size_t)ROWS * VV;
    if ((size_t)out_size > nlog) {
        loss_kernel<<<1, 256>>>(pnll, tgt, out + nlog);
    }
}

// round 17
// speedup vs baseline: 1.0486x; 1.0417x over previous
#include <cuda_runtime.h>
#include <cuda_fp16.h>
#include <math.h>
#include <stdint.h>

// Problem constants
#define BB 4
#define TT 1024
#define DD 1024
#define HH 16
#define HDIM 64
#define LL 8
#define VV 50257
#define VPAD 50432              // multiple of 256
#define NT2LM ((VPAD/256)*2)    // 394 logsumexp partials per row
#define ROWS (BB*TT)            // 4096
#define SCALE_ATT 0.07216878364870322f  // 1/sqrt(192)

// ---------------------------------------------------------------------------
// Scratch (static device globals; no runtime allocation)
// ---------------------------------------------------------------------------
__device__ float g_x   [ (size_t)ROWS * DD ];
__device__ float g_nll [ ROWS ];
__device__ float2 g_part[ (size_t)ROWS * NT2LM ];
// plain fp16 activations
__device__ __half g_qkvh[ (size_t)ROWS * 3 * DD ];
__device__ __half g_h  [ (size_t)ROWS * DD ];
__device__ __half g_y  [ (size_t)ROWS * DD ];
__device__ __half g_m  [ (size_t)ROWS * 4 * DD ];
__device__ __half g_xh [ (size_t)ROWS * DD ];
// fp16 transposed weights ([N,K] row-major)
__device__ __half g_wqkvT [ (size_t)LL * 3*DD * DD ];
__device__ __half g_wprojT[ (size_t)LL * DD * DD ];
__device__ __half g_w1T   [ (size_t)LL * 4*DD * DD ];
__device__ __half g_w2T   [ (size_t)LL * DD * 4*DD ];
__device__ __half g_lmwT  [ (size_t)VPAD * DD ];

// ---------------------------------------------------------------------------
// helpers
// ---------------------------------------------------------------------------
__device__ __forceinline__ uint32_t smem_u32(const void* p) {
    uint32_t a;
    asm("{ .reg .u64 t; cvta.to.shared.u64 t, %1; cvt.u32.u64 %0, t; }"
        : "=r"(a) : "l"(p));
    return a;
}
__device__ __forceinline__ uint32_t pack2(float x, float y) {
    __half hx = __float2half_rn(x);
    __half hy = __float2half_rn(y);
    return (uint32_t)__half_as_ushort(hx) | ((uint32_t)__half_as_ushort(hy) << 16);
}

#define MMA_F32(d, a, b) \
    asm volatile("mma.sync.aligned.m16n8k16.row.col.f32.f16.f16.f32 " \
        "{%0,%1,%2,%3}, {%4,%5,%6,%7}, {%8,%9}, {%0,%1,%2,%3};" \
        : "+f"((d)[0]), "+f"((d)[1]), "+f"((d)[2]), "+f"((d)[3]) \
        : "r"((a)[0]), "r"((a)[1]), "r"((a)[2]), "r"((a)[3]), \
          "r"((b)[0]), "r"((b)[1]))

#define LDSM4(r0, r1, r2, r3, addr) \
    asm volatile("ldmatrix.sync.aligned.m8n8.x4.shared.b16 {%0,%1,%2,%3}, [%4];" \
        : "=r"(r0), "=r"(r1), "=r"(r2), "=r"(r3) : "r"(addr))

#define LDSM4T(r0, r1, r2, r3, addr) \
    asm volatile("ldmatrix.sync.aligned.m8n8.x4.trans.shared.b16 {%0,%1,%2,%3}, [%4];" \
        : "=r"(r0), "=r"(r1), "=r"(r2), "=r"(r3) : "r"(addr))

__device__ __forceinline__ void cp16(uint32_t d, const void* g) {
    asm volatile("cp.async.cg.shared.global [%0], [%1], 16;" :: "r"(d), "l"(g));
}
#define CP_COMMIT() asm volatile("cp.async.commit_group;" ::: "memory")
#define CP_WAIT0()  asm volatile("cp.async.wait_group 0;" ::: "memory")
#define CP_WAIT1()  asm volatile("cp.async.wait_group 1;" ::: "memory")
#define CP_WAIT2()  asm volatile("cp.async.wait_group 2;" ::: "memory")

// ---------------------------------------------------------------------------
// fp16 tensor GEMM: C[M,N] = A[M,K] @ Bt[N,K]^T (+bias)(+relu/+res)
// CTA tile 128x256, K-chunk 64, 4-stage cp.async (1 sync/chunk), 512 threads.
// EPI: 0=bias->f32 (+opt lse partials), 1=bias+relu->fp16,
//      2=+res->f32 (+opt fp16 dual-write), 3=bias->fp16.
// Requires K >= 192 (nch >= 3); all call sites have K in {1024, 4096}.
// ---------------------------------------------------------------------------
#define PITCH 144
#define ATILE (128*PITCH)        // 18432
#define BTILE (256*PITCH)        // 36864
#define BUFB  (ATILE + BTILE)    // 55296
#define SMEM_DYN (4*BUFB)        // 221184; epilogue Cs (128*264*4=135168) fits

template<int EPI>
__global__ __launch_bounds__(512) void hgemm_kernel(
    int M, int N, int K,
    const __half* __restrict__ A, const __half* __restrict__ Bt,
    const float* __restrict__ bias, const float* __restrict__ res,
    float* __restrict__ C, __half* __restrict__ Ch,
    float2* __restrict__ part)
{
    extern __shared__ __align__(128) char smem[];
    const uint32_t sb = smem_u32(smem);
    const int tid  = threadIdx.x;
    const int wid  = tid >> 5;
    const int lane = tid & 31;
    const int mbase = blockIdx.x * 128;
    const int nbase = blockIdx.y * 256;
    const int warp_m = wid & 3;
    const int warp_n = wid >> 2;
    const int g = lane >> 2;
    const int q = lane & 3;

    const uint32_t aoff = (uint32_t)(warp_m*32 + (lane & 15)) * PITCH
                        + ((lane >> 4) & 1) * 16;
    const uint32_t boff = ATILE
                        + (uint32_t)(warp_n*64 + (lane & 7) + ((lane >> 4) & 1)*8) * PITCH
                        + ((lane >> 3) & 1) * 16;

    float acc[2][8][4];
    #pragma unroll
    for (int m = 0; m < 2; m++)
        #pragma unroll
        for (int n = 0; n < 8; n++)
            #pragma unroll
            for (int r = 0; r < 4; r++) acc[m][n][r] = 0.0f;

    const int nch = K >> 6;

    auto issue = [&](uint32_t dstbase, int k0) {
        #pragma unroll
        for (int i = 0; i < 2; i++) {
            int v = i*512 + tid;
            int row = v >> 3, seg = v & 7;
            cp16(dstbase + (uint32_t)row*PITCH + seg*16,
                 A + (size_t)(mbase+row)*K + k0 + seg*8);
        }
        #pragma unroll
        for (int i = 0; i < 4; i++) {
            int v = i*512 + tid;
            int row = v >> 3, seg = v & 7;
            cp16(dstbase + ATILE + (uint32_t)row*PITCH + seg*16,
                 Bt + (size_t)(nbase+row)*K + k0 + seg*8);
        }
    };

    // prologue: 3 chunks in flight (nch >= 3 always here)
    issue(sb, 0);
    CP_COMMIT();
    issue(sb + BUFB, 64);
    CP_COMMIT();
    issue(sb + 2*BUFB, 128);
    CP_COMMIT();

    for (int it = 0; it < nch; it++) {
        if (it >= nch - 1)      { CP_WAIT0(); }
        else if (it == nch - 2) { CP_WAIT1(); }
        else                    { CP_WAIT2(); }
        __syncthreads();     // releases buf (it-1)%4 AND publishes buf it%4
        if (it + 3 < nch) {
            issue(sb + (uint32_t)((it+3) & 3) * BUFB, (it+3) << 6);
            CP_COMMIT();
        }

        const uint32_t bufu = sb + (uint32_t)(it & 3) * BUFB;

        #pragma unroll
        for (int ks = 0; ks < 64; ks += 16) {
            uint32_t ar[2][4], bh[8][2];
            #pragma unroll
            for (int m = 0; m < 2; m++) {
                uint32_t ad = bufu + aoff + m*(16*PITCH) + ks*2;
                LDSM4(ar[m][0], ar[m][1], ar[m][2], ar[m][3], ad);
            }
            #pragma unroll
            for (int n2 = 0; n2 < 4; n2++) {
                uint32_t bd = bufu + boff + (uint32_t)n2*(16*PITCH) + ks*2;
                uint32_t r0, r1, r2, r3;
                LDSM4(r0, r1, r2, r3, bd);
                bh[n2*2][0] = r0; bh[n2*2][1] = r1;
                bh[n2*2+1][0] = r2; bh[n2*2+1][1] = r3;
            }
            #pragma unroll
            for (int m = 0; m < 2; m++)
                #pragma unroll
                for (int n = 0; n < 8; n++)
                    MMA_F32(acc[m][n], ar[m], bh[n]);
        }
        // no trailing sync: next iteration's top sync protects buffer reuse
    }
    __syncthreads();

    // single-pass epilogue: full 256-col tile staged through smem
    float* Cs = (float*)smem;   // [128][264]
    {
        int cb = warp_n*64;
        #pragma unroll
        for (int m = 0; m < 2; m++) {
            int r0 = warp_m*32 + m*16 + g;
            #pragma unroll
            for (int n = 0; n < 8; n++) {
                int col = cb + n*8 + 2*q;
                Cs[r0*264 + col]       = acc[m][n][0];
                Cs[r0*264 + col + 1]   = acc[m][n][1];
                Cs[(r0+8)*264 + col]   = acc[m][n][2];
                Cs[(r0+8)*264 + col+1] = acc[m][n][3];
            }
        }
    }
    __syncthreads();

    if (EPI == 1 || EPI == 3) {
        #pragma unroll
        for (int i = 0; i < 16; i++) {
            int u = tid + i*512;
            int row = u >> 6, c4 = (u & 63) * 4;
            int col = nbase + c4;
            float v0 = Cs[row*264 + c4 + 0] + bias[col];
            float v1 = Cs[row*264 + c4 + 1] + bias[col+1];
            float v2 = Cs[row*264 + c4 + 2] + bias[col+2];
            float v3 = Cs[row*264 + c4 + 3] + bias[col+3];
            if (EPI == 1) {
                v0 = fmaxf(v0, 0.f); v1 = fmaxf(v1, 0.f);
                v2 = fmaxf(v2, 0.f); v3 = fmaxf(v3, 0.f);
            }
            uint2 hv;
            hv.x = pack2(v0, v1);
            hv.y = pack2(v2, v3);
            *(uint2*)(Ch + (size_t)(mbase+row)*N + col) = hv;
        }
    } else if ((N & 3) == 0) {
        #pragma unroll
        for (int i = 0; i < 16; i++) {
            int u = tid + i*512;
            int row = u >> 6, c4 = (u & 63) * 4;
            int col = nbase + c4;
            float v0 = Cs[row*264 + c4 + 0];
            float v1 = Cs[row*264 + c4 + 1];
            float v2 = Cs[row*264 + c4 + 2];
            float v3 = Cs[row*264 + c4 + 3];
            if (bias) { v0 += bias[col]; v1 += bias[col+1]; v2 += bias[col+2]; v3 += bias[col+3]; }
            if (EPI == 2) {
                const float4 rv = *(const float4*)(res + (size_t)(mbase+row)*N + col);
                v0 += rv.x; v1 += rv.y; v2 += rv.z; v3 += rv.w;
            }
            *(float4*)(C + (size_t)(mbase+row)*N + col) = make_float4(v0, v1, v2, v3);
            if (EPI == 2 && Ch != nullptr) {
                uint2 hv;
                hv.x = pack2(v0, v1);
                hv.y = pack2(v2, v3);
                *(uint2*)(Ch + (size_t)(mbase+row)*N + col) = hv;
            }
        }
    } else {
        // ragged-N path (LM head); each warp covers one 128-col half of a row
        #pragma unroll
        for (int i = 0; i < 16; i++) {
            int u = tid + i*512;
            int row = u >> 6, c4 = (u & 63) * 4;
            float* crow = C + (size_t)(mbase+row)*N;
            float v[4];
            #pragma unroll
            for (int j = 0; j < 4; j++) {
                int col = nbase + c4 + j;
                if (col < N) {
                    float vv = Cs[row*264 + c4 + j];
                    if (bias) vv += bias[col];
                    crow[col] = vv;
                    v[j] = vv;
                } else {
                    v[j] = -1e30f;
                }
            }
            if (EPI == 0 && part != nullptr) {
                float lm = fmaxf(fmaxf(v[0], v[1]), fmaxf(v[2], v[3]));
                #pragma unroll
                for (int o2 = 16; o2 > 0; o2 >>= 1)
                    lm = fmaxf(lm, __shfl_xor_sync(0xffffffffu, lm, o2));
                float ps = 0.0f;
                #pragma unroll
                for (int j = 0; j < 4; j++)
                    if (nbase + c4 + j < N) ps += __expf(v[j] - lm);
                #pragma unroll
                for (int o2 = 16; o2 > 0; o2 >>= 1)
                    ps += __shfl_xor_sync(0xffffffffu, ps, o2);
                if (lane == 0)
                    part[(size_t)(mbase+row)*NT2LM + blockIdx.y*2 + (c4 >> 7)]
                        = make_float2(lm, ps);
            }
        }
    }
}

// ---------------------------------------------------------------------------
// Tiled transpose to fp16: in [K,N] -> out [Npad,K], zero-pad rows >= N.
// ---------------------------------------------------------------------------
__global__ __launch_bounds__(256) void tp_kernel(
    const float* __restrict__ in, __half* __restrict__ out,
    int K, int N, int Npad, size_t inStride, size_t outStride)
{
    __shared__ float t[32][33];
    const float* ip = in + blockIdx.z * inStride;
    __half* op = out + blockIdx.z * outStride;
    int n0 = blockIdx.x * 32, k0 = blockIdx.y * 32;
    int tx = threadIdx.x & 31, ty = threadIdx.x >> 5;
    #pragma unroll
    for (int j = ty; j < 32; j += 8) {
        int k = k0 + j, n = n0 + tx;
        t[j][tx] = (k < K && n < N) ? ip[(size_t)k * N + n] : 0.0f;
    }
    __syncthreads();
    {
        int nl = threadIdx.x >> 3;
        int kk = (threadIdx.x & 7) * 4;
        int n = n0 + nl, k = k0 + kk;
        if (n < Npad) {
            uint2 hv;
            hv.x = pack2(t[kk+0][nl], t[kk+1][nl]);
            hv.y = pack2(t[kk+2][nl], t[kk+3][nl]);
            *(uint2*)(op + (size_t)n * K + k) = hv;
        }
    }
}

// ---------------------------------------------------------------------------
// Embedding
// ---------------------------------------------------------------------------
__global__ __launch_bounds__(256) void embed_kernel(
    const int* __restrict__ idx, const float* __restrict__ tok,
    const float* __restrict__ pos, float* __restrict__ x)
{
    int row = blockIdx.x;
    int t   = row & (TT - 1);
    int id  = idx[row];
    const float4* tp = (const float4*)(tok + (size_t)id * DD);
    const float4* pp = (const float4*)(pos + (size_t)t  * DD);
    float4*       xp = (float4*)(x + (size_t)row * DD);
    int i = threadIdx.x;
    float4 a = tp[i], b = pp[i];
    a.x += b.x; a.y += b.y; a.z += b.z; a.w += b.w;
    xp[i] = a;
}

// ---------------------------------------------------------------------------
// LayerNorm -> fp16, warp-shuffle reduction
// ---------------------------------------------------------------------------
__global__ __launch_bounds__(256) void ln_kernel(
    const float* __restrict__ x, const float* __restrict__ g,
    const float* __restrict__ b, __half* __restrict__ oh)
{
    __shared__ float sw[8];
    __shared__ float ssw[8];
    int row = blockIdx.x;
    int tid = threadIdx.x;
    float4 v = ((const float4*)(x + (size_t)row * DD))[tid];
    float s  = v.x + v.y + v.z + v.w;
    float ss = v.x*v.x + v.y*v.y + v.z*v.z + v.w*v.w;
    #pragma unroll
    for (int o = 16; o > 0; o >>= 1) {
        s  += __shfl_xor_sync(0xffffffffu, s, o);
        ss += __shfl_xor_sync(0xffffffffu, ss, o);
    }
    if ((tid & 31) == 0) { sw[tid >> 5] = s; ssw[tid >> 5] = ss; }
    __syncthreads();
    float ts = 0.0f, tss = 0.0f;
    #pragma unroll
    for (int w = 0; w < 8; w++) { ts += sw[w]; tss += ssw[w]; }
    float mu   = ts * (1.0f / DD);
    float var  = tss * (1.0f / DD) - mu * mu;
    float rstd = rsqrtf(var + 1e-5f);
    float4 gv = ((const float4*)g)[tid];
    float4 bv = ((const float4*)b)[tid];
    float o0 = (v.x - mu) * rstd * gv.x + bv.x;
    float o1 = (v.y - mu) * rstd * gv.y + bv.y;
    float o2 = (v.z - mu) * rstd * gv.z + bv.z;
    float o3 = (v.w - mu) * rstd * gv.w + bv.w;
    uint2 hv;
    hv.x = pack2(o0, o1);
    hv.y = pack2(o2, o3);
    *(uint2*)(oh + (size_t)row * DD + tid * 4) = hv;
}

// ---------------------------------------------------------------------------
// Tensor-core flash attention, fp16 qkv, double-buffered cp.async K/V.
// Longest q-tiles scheduled first (reverse blockIdx.y mapping).
// Block = 128 threads (4 warps): one (b,h), 64-query tile. Grid (B*H, T/64).
// ---------------------------------------------------------------------------
#define APITCH 144
#define ATILE2 (64*APITCH)       // 9216

__global__ __launch_bounds__(128) void attn_kernel(
    const __half* __restrict__ qkv, __half* __restrict__ yh)
{
    __shared__ __align__(16) char sm[5 * ATILE2];   // Q | K0 K1 | V0 V1
    const uint32_t sbase = smem_u32(sm);

    const int tid  = threadIdx.x;
    const int wid  = tid >> 5;
    const int lane = tid & 31;
    const int g = lane >> 2;
    const int q = lane & 3;
    const int bh = blockIdx.x;
    const int b  = bh >> 4;
    const int h  = bh & (HH - 1);
    const int qt = gridDim.y - 1 - blockIdx.y;   // longest tiles first
    const int qbase = qt * 64;

    auto issue = [&](int kt) {
        const int bsel = kt & 1;
        const int kbase = kt * 64;
        #pragma unroll
        for (int i = 0; i < 4; i++) {
            int v = i*128 + tid;
            int row = v >> 3, seg = v & 7;
            const __half* src = qkv + (size_t)(b*TT + kbase + row)*(3*DD)
                              + DD + h*HDIM + seg*8;
            uint32_t doff = (uint32_t)row*APITCH + seg*16;
            cp16(sbase + (1+bsel)*ATILE2 + doff, src);        // K
            cp16(sbase + (3+bsel)*ATILE2 + doff, src + DD);   // V
        }
    };

    {
        #pragma unroll
        for (int i = 0; i < 4; i++) {
            int v = i*128 + tid;
            int row = v >> 3, seg = v & 7;
            cp16(sbase + (uint32_t)row*APITCH + seg*16,
                 qkv + (size_t)(b*TT + qbase + row)*(3*DD) + h*HDIM + seg*8);
        }
        issue(0);
        CP_COMMIT();
    }

    const int qrow0 = qbase + wid*16 + g;
    const int qrow1 = qrow0 + 8;

    uint32_t qa[4][4];
    float m0 = -1e30f, m1 = -1e30f, l0 = 0.0f, l1 = 0.0f;
    float oacc[8][4];
    #pragma unroll
    for (int n = 0; n < 8; n++)
        #pragma unroll
        for (int r = 0; r < 4; r++) oacc[n][r] = 0.0f;

    const uint32_t kfl = (uint32_t)((lane & 7) + ((lane >> 4) & 1)*8)*APITCH
                       + ((lane >> 3) & 1) * 16;
    const uint32_t vfl = (uint32_t)((lane & 7) + ((lane >> 3) & 1)*8)*APITCH
                       + ((lane >> 4) & 1) * 16;

    const int ntiles = qt + 1;
    for (int kt = 0; kt < ntiles; kt++) {
        const int kbase = kt * 64;
        if (kt + 1 < ntiles) {
            issue(kt + 1);
            CP_COMMIT();
            CP_WAIT1();
        } else {
            CP_WAIT0();
        }
        __syncthreads();

        if (kt == 0) {
            uint32_t qaddr = sbase + (uint32_t)(wid*16 + (lane & 15))*APITCH
                           + ((lane >> 4) & 1) * 16;
            #pragma unroll
            for (int c = 0; c < 4; c++)
                LDSM4(qa[c][0], qa[c][1], qa[c][2], qa[c][3], qaddr + c*32);
        }

        const uint32_t kfr = sbase + (1 + (kt & 1))*ATILE2 + kfl;
        const uint32_t vfr = sbase + (3 + (kt & 1))*ATILE2 + vfl;

        float s[8][4];
        #pragma unroll
        for (int n = 0; n < 8; n++)
            #pragma unroll
            for (int r = 0; r < 4; r++) s[n][r] = 0.0f;
        #pragma unroll
        for (int kc = 0; kc < 4; kc++) {
            #pragma unroll
            for (int n2 = 0; n2 < 4; n2++) {
                uint32_t r0, r1, r2, r3;
                LDSM4(r0, r1, r2, r3, kfr + (uint32_t)n2*(16*APITCH) + kc*32);
                uint32_t kb0[2] = {r0, r1};
                uint32_t kb1[2] = {r2, r3};
                MMA_F32(s[n2*2],   qa[kc], kb0);
                MMA_F32(s[n2*2+1], qa[kc], kb1);
            }
        }

        #pragma unroll
        for (int n = 0; n < 8; n++) {
            int k0 = kbase + n*8 + 2*q;
            s[n][0] = (k0     <= qrow0) ? s[n][0]*SCALE_ATT : -1e30f;
            s[n][1] = (k0 + 1 <= qrow0) ? s[n][1]*SCALE_ATT : -1e30f;
            s[n][2] = (k0     <= qrow1) ? s[n][2]*SCALE_ATT : -1e30f;
            s[n][3] = (k0 + 1 <= qrow1) ? s[n][3]*SCALE_ATT : -1e30f;
        }

        float mx0 = -1e30f, mx1 = -1e30f;
        #pragma unroll
        for (int n = 0; n < 8; n++) {
            mx0 = fmaxf(mx0, fmaxf(s[n][0], s[n][1]));
            mx1 = fmaxf(mx1, fmaxf(s[n][2], s[n][3]));
        }
        mx0 = fmaxf(mx0, __shfl_xor_sync(0xffffffffu, mx0, 1));
        mx0 = fmaxf(mx0, __shfl_xor_sync(0xffffffffu, mx0, 2));
        mx1 = fmaxf(mx1, __shfl_xor_sync(0xffffffffu, mx1, 1));
        mx1 = fmaxf(mx1, __shfl_xor_sync(0xffffffffu, mx1, 2));

        float nm0 = fmaxf(m0, mx0), nm1 = fmaxf(m1, mx1);
        float cor0 = __expf(m0 - nm0), cor1 = __expf(m1 - nm1);
        m0 = nm0; m1 = nm1;
        l0 *= cor0; l1 *= cor1;
        #pragma unroll
        for (int n = 0; n < 8; n++) {
            oacc[n][0] *= cor0; oacc[n][1] *= cor0;
            oacc[n][2] *= cor1; oacc[n][3] *= cor1;
        }

        float sum0 = 0.0f, sum1 = 0.0f;
        #pragma unroll
        for (int n = 0; n < 8; n++) {
            s[n][0] = __expf(s[n][0] - nm0); sum0 += s[n][0];
            s[n][1] = __expf(s[n][1] - nm0); sum0 += s[n][1];
            s[n][2] = __expf(s[n][2] - nm1); sum1 += s[n][2];
            s[n][3] = __expf(s[n][3] - nm1); sum1 += s[n][3];
        }
        sum0 += __shfl_xor_sync(0xffffffffu, sum0, 1);
        sum0 += __shfl_xor_sync(0xffffffffu, sum0, 2);
        sum1 += __shfl_xor_sync(0xffffffffu, sum1, 1);
        sum1 += __shfl_xor_sync(0xffffffffu, sum1, 2);
        l0 += sum0; l1 += sum1;

        #pragma unroll
        for (int kc = 0; kc < 4; kc++) {
            uint32_t pa[4];
            pa[0] = pack2(s[2*kc][0],   s[2*kc][1]);
            pa[1] = pack2(s[2*kc][2],   s[2*kc][3]);
            pa[2] = pack2(s[2*kc+1][0], s[2*kc+1][1]);
            pa[3] = pack2(s[2*kc+1][2], s[2*kc+1][3]);
            #pragma unroll
            for (int n2 = 0; n2 < 4; n2++) {
                uint32_t r0, r1, r2, r3;
                LDSM4T(r0, r1, r2, r3, vfr + (uint32_t)kc*(16*APITCH) + n2*32);
                uint32_t vb0[2] = {r0, r1};
                uint32_t vb1[2] = {r2, r3};
                MMA_F32(oacc[n2*2],   pa, vb0);
                MMA_F32(oacc[n2*2+1], pa, vb1);
            }
        }
        __syncthreads();
    }

    float inv0 = 1.0f / l0, inv1 = 1.0f / l1;
    size_t base0 = (size_t)(b*TT + qrow0) * DD + h*HDIM;
    size_t base1 = base0 + (size_t)8 * DD;
    #pragma unroll
    for (int n = 0; n < 8; n++) {
        int col = n*8 + 2*q;
        *(uint32_t*)(yh + base0 + col) = pack2(oacc[n][0]*inv0, oacc[n][1]*inv0);
        *(uint32_t*)(yh + base1 + col) = pack2(oacc[n][2]*inv1, oacc[n][3]*inv1);
    }
}

// ---------------------------------------------------------------------------
// NLL from logsumexp partials + gathered target logit
// ---------------------------------------------------------------------------
__global__ __launch_bounds__(128) void nll_kernel(
    const float2* __restrict__ part, const float* __restrict__ logits,
    const int* __restrict__ tgt, float* __restrict__ nll)
{
    __shared__ float rm[128];
    __shared__ float rs[128];
    int row = blockIdx.x;
    int tid = threadIdx.x;
    const float2* pr = part + (size_t)row * NT2LM;

    float m = -1e30f, s = 0.0f;
    for (int i = tid; i < NT2LM; i += 128) {
        float2 p = pr[i];
        float M = fmaxf(m, p.x);
        s = s * __expf(m - M) + p.y * __expf(p.x - M);
        m = M;
    }
    rm[tid] = m; rs[tid] = s;
    __syncthreads();
    for (int o = 64; o > 0; o >>= 1) {
        if (tid < o) {
            float m2 = rm[tid + o], s2 = rs[tid + o];
            float M = fmaxf(rm[tid], m2);
            rs[tid] = rs[tid] * __expf(rm[tid] - M) + s2 * __expf(m2 - M);
            rm[tid] = M;
        }
        __syncthreads();
    }
    if (tid == 0) {
        float lse = rm[0] + logf(rs[0]);
        int tg = tgt[row];
        nll[row] = (tg != 0) ? (lse - logits[(size_t)row * VV + tg]) : 0.0f;
    }
}

__global__ __launch_bounds__(256) void loss_kernel(
    const float* __restrict__ nll, const int* __restrict__ tgt,
    float* __restrict__ out)
{
    __shared__ float s[256];
    __shared__ float c[256];
    int tid = threadIdx.x;
    float sv = 0.0f, cv = 0.0f;
    for (int i = tid; i < ROWS; i += 256) {
        sv += nll[i];
        cv += (tgt[i] != 0) ? 1.0f : 0.0f;
    }
    s[tid] = sv; c[tid] = cv; __syncthreads();
    for (int o = 128; o > 0; o >>= 1) {
        if (tid < o) { s[tid] += s[tid+o]; c[tid] += c[tid+o]; }
        __syncthreads();
    }
    if (tid == 0) out[0] = s[0] / fmaxf(c[0], 1.0f);
}

// ---------------------------------------------------------------------------
// Launcher
// ---------------------------------------------------------------------------
extern "C" void kernel_launch(void* const* d_in, const int* in_sizes, int n_in,
                              void* d_out, int out_size)
{
    const int*   idx   = (const int*)  d_in[0];
    const int*   tgt   = (const int*)  d_in[1];
    const float* tok   = (const float*)d_in[2];
    const float* pos   = (const float*)d_in[3];
    const float* ln1g  = (const float*)d_in[4];
    const float* ln1b  = (const float*)d_in[5];
    const float* wqkv  = (const float*)d_in[6];
    const float* bqkv  = (const float*)d_in[7];
    const float* wproj = (const float*)d_in[8];
    const float* bproj = (const float*)d_in[9];
    const float* ln2g  = (const float*)d_in[10];
    const float* ln2b  = (const float*)d_in[11];
    const float* w1    = (const float*)d_in[12];
    const float* b1    = (const float*)d_in[13];
    const float* w2    = (const float*)d_in[14];
    const float* b2    = (const float*)d_in[15];
    const float* lmw   = (const float*)d_in[16];

    float *px, *pnll;
    float2 *ppart;
    __half *pqkvh, *ph, *py, *pm, *pxh;
    __half *pwqkv, *pwproj, *pw1, *pw2, *plmw;
    cudaGetSymbolAddress((void**)&px,    g_x);
    cudaGetSymbolAddress((void**)&pnll,  g_nll);
    cudaGetSymbolAddress((void**)&ppart, g_part);
    cudaGetSymbolAddress((void**)&pqkvh, g_qkvh);
    cudaGetSymbolAddress((void**)&ph,    g_h);
    cudaGetSymbolAddress((void**)&py,    g_y);
    cudaGetSymbolAddress((void**)&pm,    g_m);
    cudaGetSymbolAddress((void**)&pxh,   g_xh);
    cudaGetSymbolAddress((void**)&pwqkv, g_wqkvT);
    cudaGetSymbolAddress((void**)&pwproj,g_wprojT);
    cudaGetSymbolAddress((void**)&pw1,   g_w1T);
    cudaGetSymbolAddress((void**)&pw2,   g_w2T);
    cudaGetSymbolAddress((void**)&plmw,  g_lmwT);

    cudaFuncSetAttribute((const void*)hgemm_kernel<0>,
                         cudaFuncAttributeMaxDynamicSharedMemorySize, SMEM_DYN);
    cudaFuncSetAttribute((const void*)hgemm_kernel<1>,
                         cudaFuncAttributeMaxDynamicSharedMemorySize, SMEM_DYN);
    cudaFuncSetAttribute((const void*)hgemm_kernel<2>,
                         cudaFuncAttributeMaxDynamicSharedMemorySize, SMEM_DYN);
    cudaFuncSetAttribute((const void*)hgemm_kernel<3>,
                         cudaFuncAttributeMaxDynamicSharedMemorySize, SMEM_DYN);

    float* out = (float*)d_out;

    // weight transposes to fp16 (graph-captured each launch)
    tp_kernel<<<dim3(3*DD/32, DD/32, LL), 256>>>(
        wqkv, pwqkv, DD, 3*DD, 3*DD, (size_t)DD*3*DD, (size_t)3*DD*DD);
    tp_kernel<<<dim3(DD/32, DD/32, LL), 256>>>(
        wproj, pwproj, DD, DD, DD, (size_t)DD*DD, (size_t)DD*DD);
    tp_kernel<<<dim3(4*DD/32, DD/32, LL), 256>>>(
        w1, pw1, DD, 4*DD, 4*DD, (size_t)DD*4*DD, (size_t)4*DD*DD);
    tp_kernel<<<dim3(DD/32, 4*DD/32, LL), 256>>>(
        w2, pw2, 4*DD, DD, DD, (size_t)4*DD*DD, (size_t)DD*4*DD);
    tp_kernel<<<dim3(VPAD/32, DD/32, 1), 256>>>(
        lmw, plmw, DD, VV, VPAD, 0, 0);

    embed_kernel<<<ROWS, 256>>>(idx, tok, pos, px);

    for (int l = 0; l < LL; l++) {
        ln_kernel<<<ROWS, 256>>>(px, ln1g + (size_t)l*DD, ln1b + (size_t)l*DD, ph);
        hgemm_kernel<3><<<dim3(ROWS/128, 3*DD/256), 512, SMEM_DYN>>>(
            ROWS, 3*DD, DD, ph, pwqkv + (size_t)l*3*DD*DD,
            bqkv + (size_t)l*3*DD, nullptr, nullptr, pqkvh, nullptr);
        attn_kernel<<<dim3(BB*HH, TT/64), 128>>>(pqkvh, py);
        hgemm_kernel<2><<<dim3(ROWS/128, DD/256), 512, SMEM_DYN>>>(
            ROWS, DD, DD, py, pwproj + (size_t)l*DD*DD,
            bproj + (size_t)l*DD, px, px, nullptr, nullptr);
        ln_kernel<<<ROWS, 256>>>(px, ln2g + (size_t)l*DD, ln2b + (size_t)l*DD, ph);
        hgemm_kernel<1><<<dim3(ROWS/128, 4*DD/256), 512, SMEM_DYN>>>(
            ROWS, 4*DD, DD, ph, pw1 + (size_t)l*4*DD*DD,
            b1 + (size_t)l*4*DD, nullptr, nullptr, pm, nullptr);
        // last layer: dual-write fp16 residual for LM head
        hgemm_kernel<2><<<dim3(ROWS/128, DD/256), 512, SMEM_DYN>>>(
            ROWS, DD, 4*DD, pm, pw2 + (size_t)l*DD*4*DD,
            b2 + (size_t)l*DD, px, px,
            (l == LL-1) ? pxh : nullptr, nullptr);
    }

    // logits = x @ lm_w (+ fused logsumexp partials)
    hgemm_kernel<0><<<dim3(ROWS/128, VPAD/256), 512, SMEM_DYN>>>(
        ROWS, VV, DD, pxh, plmw, nullptr, nullptr, out, nullptr, ppart);

    // loss from partials
    nll_kernel<<<ROWS, 128>>>(ppart, out, tgt, pnll);
    size_t nlog = (size_t)ROWS * VV;
    if ((size_t)out_size > nlog) {
        loss_kernel<<<1, 256>>>(pnll, tgt, out + nlog);
    }
}